// round 13
// baseline (speedup 1.0000x reference)
#include <cuda_runtime.h>
#include <cuda_bf16.h>

#define S_TOTAL 15768
#define NQ 300
#define C_MODEL 256
#define NHEADS 8
#define DHEAD 32
#define NLAYERS 6
#define DFF 1024
#define CHUNK 256
#define NCHUNK 62
#define SW 493
#define FLASH_SMEM_BYTES 65536

// ------------------------- scratch (device globals) -------------------------
__device__ float g_srct[S_TOTAL * C_MODEL];
__device__ float g_srcpos[S_TOTAL * C_MODEL];
__device__ unsigned g_mbits[NQ * SW];
__device__ float g_kvall[(size_t)NLAYERS * S_TOTAL * 512];
__device__ float g_opart[(size_t)NCHUNK * NHEADS * NQ * DHEAD];
__device__ float2 g_mspart[NCHUNK * NHEADS * NQ];
__device__ float g_x[NQ * C_MODEL];
__device__ float g_qe[NQ * C_MODEL];
__device__ float g_qkv[NQ * 3 * C_MODEL];
__device__ float g_qb[NQ * C_MODEL];
__device__ float g_ao[NQ * C_MODEL];
__device__ float g_t2[NQ * C_MODEL];
__device__ float g_ffh[NQ * DFF];
__device__ float g_part[660000];          // split-K partials (max 160 tiles * 4096)
__device__ unsigned g_ticket[128];        // zero-init; self-resetting
__device__ int   g_mask_float;
__device__ int   g_mask_byte;

// ------------------------- bf16x3 helpers -------------------------
__device__ __forceinline__ void split2(float x, float y, unsigned& hi, unsigned& lo)
{
    __nv_bfloat16 hx = __float2bfloat16(x);
    __nv_bfloat16 hy = __float2bfloat16(y);
    float rx = x - __bfloat162float(hx);
    float ry = y - __bfloat162float(hy);
    __nv_bfloat16 lx = __float2bfloat16(rx);
    __nv_bfloat16 ly = __float2bfloat16(ry);
    hi = (unsigned)__bfloat16_as_ushort(hx) | ((unsigned)__bfloat16_as_ushort(hy) << 16);
    lo = (unsigned)__bfloat16_as_ushort(lx) | ((unsigned)__bfloat16_as_ushort(ly) << 16);
}

__device__ __forceinline__ void mma16(float c[4], const unsigned a[4], const unsigned b[2])
{
    asm volatile(
        "mma.sync.aligned.m16n8k16.row.col.f32.bf16.bf16.f32 "
        "{%0,%1,%2,%3}, {%4,%5,%6,%7}, {%8,%9}, {%0,%1,%2,%3};"
        : "+f"(c[0]), "+f"(c[1]), "+f"(c[2]), "+f"(c[3])
        : "r"(a[0]), "r"(a[1]), "r"(a[2]), "r"(a[3]), "r"(b[0]), "r"(b[1]));
}

// ------------------------- pipelined bf16x3 GEMM with split-K -------------------------
// C[M,N] = act( alpha_col * (A[M,K] @ B[N,K]^T + bias[N]) )
// blockIdx.z = z * KS + kz. KS>1 only supported for BM=64 (MT=1):
// partial-store + ticket; last CTA reduces in fixed kz order (deterministic).
template <int BM>
__global__ __launch_bounds__(256) void gemmbf(
    const float* __restrict__ A0, const float* __restrict__ A1,
    const float* __restrict__ Aadd, int nsplit,
    const float* __restrict__ B, const float* __restrict__ bias,
    float* __restrict__ Cc, int M, int N, int K,
    int lda, int ldb, int ldc,
    long sA, long sB, long sbias, long sC,
    float alpha, int nscale, int relu,
    int KS, float* __restrict__ Part, unsigned* __restrict__ Ticket)
{
    constexpr int BN = 64;
    constexpr int WMR = BM / 4;
    constexpr int MT = WMR / 16;
    constexpr int NT = 4;
    constexpr int NAROW = BM / 32;
    __shared__ unsigned Ah[BM][17], Al[BM][17];
    __shared__ unsigned Bh[BN][17], Bl[BN][17];

    int bz = blockIdx.z;
    int z = bz / KS, kz = bz % KS;
    int Kc = K / KS, kbeg = kz * Kc, kend = kbeg + Kc;
    int m0 = blockIdx.y * BM, n0 = blockIdx.x * BN;
    const float* A = ((n0 >= nsplit) ? A1 : A0) + (long)z * sA;
    const float* Aa = (n0 < nsplit) ? Aadd : nullptr;
    const float* Bp = B + (long)z * sB;
    const float* bp = bias ? bias + (long)z * sbias : nullptr;
    float* Cp = Cc + (long)z * sC;

    int tid = threadIdx.x;
    int warp = tid >> 5, lane = tid & 31;
    int gid = lane >> 2, ctg = lane & 3;
    int wm = warp & 3, wn = warp >> 2;
    int mw = wm * WMR, nw = wn * 32;
    int lr = tid >> 3, lc4 = tid & 7;

    float acc[MT][NT][4] = {};
    float4 pa[NAROW], pb[2];

    #pragma unroll
    for (int i = 0; i < NAROW; i++) {
        int row = i * 32 + lr;
        float4 v = make_float4(0.f, 0.f, 0.f, 0.f);
        if (m0 + row < M) {
            v = *(const float4*)&A[(long)(m0 + row) * lda + kbeg + lc4 * 4];
            if (Aa) {
                float4 w = *(const float4*)&Aa[(long)(m0 + row) * lda + kbeg + lc4 * 4];
                v.x += w.x; v.y += w.y; v.z += w.z; v.w += w.w;
            }
        }
        pa[i] = v;
    }
    #pragma unroll
    for (int i = 0; i < 2; i++) {
        int row = i * 32 + lr;
        pb[i] = make_float4(0.f, 0.f, 0.f, 0.f);
        if (n0 + row < N)
            pb[i] = *(const float4*)&Bp[(long)(n0 + row) * ldb + kbeg + lc4 * 4];
    }

    for (int k0 = kbeg; k0 < kend; k0 += 32) {
        __syncthreads();
        #pragma unroll
        for (int i = 0; i < NAROW; i++) {
            int row = i * 32 + lr;
            unsigned h0, l0, h1, l1;
            split2(pa[i].x, pa[i].y, h0, l0);
            split2(pa[i].z, pa[i].w, h1, l1);
            Ah[row][lc4 * 2] = h0;     Al[row][lc4 * 2] = l0;
            Ah[row][lc4 * 2 + 1] = h1; Al[row][lc4 * 2 + 1] = l1;
        }
        #pragma unroll
        for (int i = 0; i < 2; i++) {
            int row = i * 32 + lr;
            unsigned h0, l0, h1, l1;
            split2(pb[i].x, pb[i].y, h0, l0);
            split2(pb[i].z, pb[i].w, h1, l1);
            Bh[row][lc4 * 2] = h0;     Bl[row][lc4 * 2] = l0;
            Bh[row][lc4 * 2 + 1] = h1; Bl[row][lc4 * 2 + 1] = l1;
        }
        __syncthreads();

        int kn = k0 + 32;
        if (kn < kend) {
            #pragma unroll
            for (int i = 0; i < NAROW; i++) {
                int row = i * 32 + lr;
                float4 v = make_float4(0.f, 0.f, 0.f, 0.f);
                if (m0 + row < M) {
                    v = *(const float4*)&A[(long)(m0 + row) * lda + kn + lc4 * 4];
                    if (Aa) {
                        float4 w = *(const float4*)&Aa[(long)(m0 + row) * lda + kn + lc4 * 4];
                        v.x += w.x; v.y += w.y; v.z += w.z; v.w += w.w;
                    }
                }
                pa[i] = v;
            }
            #pragma unroll
            for (int i = 0; i < 2; i++) {
                int row = i * 32 + lr;
                float4 v = make_float4(0.f, 0.f, 0.f, 0.f);
                if (n0 + row < N)
                    v = *(const float4*)&Bp[(long)(n0 + row) * ldb + kn + lc4 * 4];
                pb[i] = v;
            }
        }

        #pragma unroll
        for (int st = 0; st < 2; st++) {
            int kc = st * 8;
            unsigned bh[NT][2], bl[NT][2];
            #pragma unroll
            for (int nt = 0; nt < NT; nt++) {
                int row = nw + nt * 8 + gid;
                bh[nt][0] = Bh[row][kc + ctg];
                bh[nt][1] = Bh[row][kc + ctg + 4];
                bl[nt][0] = Bl[row][kc + ctg];
                bl[nt][1] = Bl[row][kc + ctg + 4];
            }
            #pragma unroll
            for (int mt = 0; mt < MT; mt++) {
                int r0 = mw + mt * 16 + gid, r1 = r0 + 8;
                unsigned ah[4], al[4];
                ah[0] = Ah[r0][kc + ctg];     ah[1] = Ah[r1][kc + ctg];
                ah[2] = Ah[r0][kc + ctg + 4]; ah[3] = Ah[r1][kc + ctg + 4];
                al[0] = Al[r0][kc + ctg];     al[1] = Al[r1][kc + ctg];
                al[2] = Al[r0][kc + ctg + 4]; al[3] = Al[r1][kc + ctg + 4];
                #pragma unroll
                for (int nt = 0; nt < NT; nt++) {
                    mma16(acc[mt][nt], ah, bh[nt]);
                    mma16(acc[mt][nt], al, bh[nt]);
                    mma16(acc[mt][nt], ah, bl[nt]);
                }
            }
        }
    }

    if (BM == 64 && KS > 1) {
        int tileId = (z * gridDim.y + blockIdx.y) * gridDim.x + blockIdx.x;
        long pbase = ((long)tileId * KS + kz) * 4096;
        #pragma unroll
        for (int nt = 0; nt < NT; nt++)
            #pragma unroll
            for (int e = 0; e < 4; e++)
                Part[pbase + tid * 16 + nt * 4 + e] = acc[0][nt][e];
        __syncthreads();
        __shared__ int lastf;
        if (tid == 0) {
            __threadfence();
            lastf = (atomicAdd(&Ticket[tileId], 1u) == (unsigned)(KS - 1));
        }
        __syncthreads();
        if (!lastf) return;
        __threadfence();
        float sum[16] = {};
        for (int k2 = 0; k2 < KS; k2++) {
            if (k2 == kz) {
                #pragma unroll
                for (int nt = 0; nt < NT; nt++)
                    #pragma unroll
                    for (int e = 0; e < 4; e++)
                        sum[nt * 4 + e] += acc[0][nt][e];
            } else {
                long b2 = ((long)tileId * KS + k2) * 4096 + tid * 16;
                #pragma unroll
                for (int j = 0; j < 16; j++)
                    sum[j] += Part[b2 + j];
            }
        }
        if (tid == 0) Ticket[tileId] = 0;
        #pragma unroll
        for (int nt = 0; nt < NT; nt++) {
            #pragma unroll
            for (int e = 0; e < 4; e++) {
                int m = m0 + mw + gid + (e >> 1) * 8;
                int n = n0 + nw + nt * 8 + 2 * ctg + (e & 1);
                if (m >= M || n >= N) continue;
                float v = sum[nt * 4 + e];
                if (bp) v += bp[n];
                if (n < nscale) v *= alpha;
                if (relu) v = fmaxf(v, 0.f);
                Cp[(long)m * ldc + n] = v;
            }
        }
        return;
    }

    #pragma unroll
    for (int mt = 0; mt < MT; mt++) {
        #pragma unroll
        for (int nt = 0; nt < NT; nt++) {
            #pragma unroll
            for (int e = 0; e < 4; e++) {
                int m = m0 + mw + mt * 16 + gid + (e >> 1) * 8;
                int n = n0 + nw + nt * 8 + 2 * ctg + (e & 1);
                if (m >= M || n >= N) continue;
                float v = acc[mt][nt][e];
                if (bp) v += bp[n];
                if (n < nscale) v *= alpha;
                if (relu) v = fmaxf(v, 0.f);
                Cp[(long)m * ldc + n] = v;
            }
        }
    }
}

// ------------------------- residual + LayerNorm -------------------------
__global__ __launch_bounds__(256) void residual_ln(
    float* __restrict__ x, const float* __restrict__ res,
    const float* __restrict__ w, const float* __restrict__ b)
{
    int r = blockIdx.x;
    int c = threadIdx.x;
    float v = x[r * 256 + c] + res[r * 256 + c];
    __shared__ float red[256];
    red[c] = v; __syncthreads();
    for (int off = 128; off > 0; off >>= 1) { if (c < off) red[c] += red[c + off]; __syncthreads(); }
    float mean = red[0] * (1.f / 256.f);
    __syncthreads();
    float d = v - mean;
    red[c] = d * d; __syncthreads();
    for (int off = 128; off > 0; off >>= 1) { if (c < off) red[c] += red[c + off]; __syncthreads(); }
    float var = red[0] * (1.f / 256.f);
    x[r * 256 + c] = d * rsqrtf(var + 1e-5f) * w[c] + b[c];
}

// ------------------------- fused self-attention -------------------------
__global__ __launch_bounds__(256) void sa_attn(const float* __restrict__ qkv,
                                               float* __restrict__ ao)
{
    int h = blockIdx.x;
    int w = threadIdx.x >> 5;
    int lane = threadIdx.x & 31;
    int q = blockIdx.y * 8 + w;
    __shared__ float Qs[8][32];
    if (q < NQ) Qs[w][lane] = qkv[(long)q * 768 + h * 32 + lane];
    __syncwarp();
    if (q >= NQ) return;

    float m = -3.4e38f, s = 0.f, O[32] = {};
    for (int k = lane; k < NQ; k += 32) {
        const float4* Kp = (const float4*)&qkv[(long)k * 768 + 256 + h * 32];
        float d = 0.f;
        #pragma unroll
        for (int f = 0; f < 8; f++) {
            float4 kk = Kp[f];
            d += Qs[w][4*f]*kk.x + Qs[w][4*f+1]*kk.y + Qs[w][4*f+2]*kk.z + Qs[w][4*f+3]*kk.w;
        }
        float p;
        if (d > m) {
            float c = __expf(m - d);
            s = s * c + 1.f;
            #pragma unroll
            for (int i = 0; i < 32; i++) O[i] *= c;
            m = d; p = 1.f;
        } else { p = __expf(d - m); s += p; }
        const float4* Vp = (const float4*)&qkv[(long)k * 768 + 512 + h * 32];
        #pragma unroll
        for (int f = 0; f < 8; f++) {
            float4 vv = Vp[f];
            O[4*f]   += p * vv.x; O[4*f+1] += p * vv.y;
            O[4*f+2] += p * vv.z; O[4*f+3] += p * vv.w;
        }
    }
    float mg = m;
    #pragma unroll
    for (int o = 16; o; o >>= 1) mg = fmaxf(mg, __shfl_xor_sync(0xffffffffu, mg, o));
    float c = __expf(m - mg);
    s *= c;
    #pragma unroll
    for (int o = 16; o; o >>= 1) s += __shfl_xor_sync(0xffffffffu, s, o);
    float mine = 0.f;
    #pragma unroll
    for (int d = 0; d < 32; d++) {
        float v = O[d] * c;
        #pragma unroll
        for (int o = 16; o; o >>= 1) v += __shfl_xor_sync(0xffffffffu, v, o);
        if (lane == d) mine = v;
    }
    ao[(long)q * 256 + h * 32 + lane] = mine / s;
}

// ------------------------- flash cross-attention -------------------------
__global__ __launch_bounds__(320, 1) void flash_ca(
    const float* __restrict__ Qm,
    const float* __restrict__ KV,
    const unsigned* __restrict__ mbits,
    float* __restrict__ Opart, float2* __restrict__ MSpart)
{
    extern __shared__ __align__(16) float4 sh[];
    float4 (*Ks)[8] = (float4(*)[8])sh;
    float4 (*Vs)[8] = (float4(*)[8])(sh + CHUNK * 8);
    int ch = blockIdx.x, h = blockIdx.y;
    int s0 = ch * CHUNK;
    int nk = min(CHUNK, S_TOTAL - s0);
    int tid = threadIdx.x;
    for (int idx = tid; idx < nk * 8; idx += 320) {
        int j = idx >> 3, f = idx & 7;
        const float4* row = (const float4*)&KV[(long)(s0 + j) * 512];
        Ks[j][f] = row[h * 8 + f];
        Vs[j][f] = row[64 + h * 8 + f];
    }
    __syncthreads();

    int q = tid;
    if (q >= NQ) return;

    float Q[32], O[32] = {};
    #pragma unroll
    for (int f = 0; f < 8; f++)
        ((float4*)Q)[f] = *(const float4*)&Qm[(long)q * 256 + h * 32 + f * 4];
    float m = -3.4e38f, s = 0.f;

    for (int jw = 0; jw < nk; jw += 32) {
        unsigned w = mbits[q * SW + ((s0 + jw) >> 5)];
        while (w) {
            int jj = __ffs(w) - 1;
            w &= w - 1;
            int j = jw + jj;
            float d = 0.f;
            #pragma unroll
            for (int f = 0; f < 8; f++) {
                float4 kk = Ks[j][f];
                d += Q[4*f]*kk.x + Q[4*f+1]*kk.y + Q[4*f+2]*kk.z + Q[4*f+3]*kk.w;
            }
            float p;
            if (d > m) {
                float c = __expf(m - d);
                s = s * c + 1.f;
                #pragma unroll
                for (int i = 0; i < 32; i++) O[i] *= c;
                m = d; p = 1.f;
            } else { p = __expf(d - m); s += p; }
            #pragma unroll
            for (int f = 0; f < 8; f++) {
                float4 vv = Vs[j][f];
                O[4*f]   += p * vv.x; O[4*f+1] += p * vv.y;
                O[4*f+2] += p * vv.z; O[4*f+3] += p * vv.w;
            }
        }
    }
    long base = (long)(ch * NHEADS + h) * NQ + q;
    float4* op = (float4*)&Opart[base * DHEAD];
    #pragma unroll
    for (int f = 0; f < 8; f++) op[f] = ((float4*)O)[f];
    MSpart[base] = make_float2(m, s);
}

// ------------------------- combine (4-way split over head dim) -------------------------
__global__ void ca_combine(const float* __restrict__ Opart,
                           const float2* __restrict__ MSpart,
                           float* __restrict__ ao)
{
    int idx = blockIdx.x * blockDim.x + threadIdx.x;
    if (idx >= NHEADS * NQ * 4) return;
    int dg = idx & 3;
    int hq = idx >> 2;
    int h = hq / NQ, q = hq % NQ;
    float m = -3.4e38f, s = 0.f;
    float O[8] = {};
    for (int ch = 0; ch < NCHUNK; ch++) {
        long base = (long)(ch * NHEADS + h) * NQ + q;
        float2 ms = MSpart[base];
        if (ms.y <= 0.f) continue;
        float c2;
        if (ms.x > m) {
            float c = (m > -3.0e38f) ? __expf(m - ms.x) : 0.f;
            s *= c;
            #pragma unroll
            for (int d = 0; d < 8; d++) O[d] *= c;
            m = ms.x;
            c2 = 1.f;
        } else {
            c2 = __expf(ms.x - m);
        }
        s += ms.y * c2;
        const float4* op = (const float4*)&Opart[base * DHEAD + dg * 8];
        float4 v0 = op[0], v1 = op[1];
        O[0] += c2 * v0.x; O[1] += c2 * v0.y; O[2] += c2 * v0.z; O[3] += c2 * v0.w;
        O[4] += c2 * v1.x; O[5] += c2 * v1.y; O[6] += c2 * v1.z; O[7] += c2 * v1.w;
    }
    float inv = 1.f / s;
    float4* outp = (float4*)&ao[(long)q * 256 + h * 32 + dg * 8];
    outp[0] = make_float4(O[0] * inv, O[1] * inv, O[2] * inv, O[3] * inv);
    outp[1] = make_float4(O[4] * inv, O[5] * inv, O[6] * inv, O[7] * inv);
}

// ------------------------- small kernels -------------------------
__global__ void prep_src(const float* __restrict__ srcs, const float* __restrict__ pos,
                         float* __restrict__ srct, float* __restrict__ srcpos)
{
    __shared__ float t1[32][33], t2[32][33];
    int s0 = blockIdx.x * 32, c0 = blockIdx.y * 32;
    int tx = threadIdx.x, ty = threadIdx.y;
    #pragma unroll
    for (int i = 0; i < 4; i++) {
        int c = c0 + ty + i * 8, s = s0 + tx;
        float a = 0.f, f = 0.f;
        if (s < S_TOTAL) { a = srcs[(long)c * S_TOTAL + s]; f = pos[(long)c * S_TOTAL + s]; }
        t1[ty + i * 8][tx] = a;
        t2[ty + i * 8][tx] = f;
    }
    __syncthreads();
    #pragma unroll
    for (int i = 0; i < 4; i++) {
        int s = s0 + ty + i * 8, c = c0 + tx;
        if (s < S_TOTAL) {
            float a = t1[tx][ty + i * 8];
            float f = t2[tx][ty + i * 8];
            srct[(long)s * 256 + c]   = a;
            srcpos[(long)s * 256 + c] = a + f;
        }
    }
}

__global__ void init_qx(const float* __restrict__ qemb, float* __restrict__ qe, float* __restrict__ x)
{
    int r = blockIdx.x, c = threadIdx.x;
    qe[r * 256 + c] = qemb[r * 512 + c];
    x[r * 256 + c]  = qemb[r * 512 + 256 + c];
}

__global__ void detect_mask(const unsigned int* __restrict__ w)
{
    if (threadIdx.x == 0) { g_mask_float = 0; g_mask_byte = 0; }
    __syncthreads();
    int fl = 0, by = 0;
    for (int i = threadIdx.x; i < 65536; i += 256) {
        unsigned int v = w[i];
        if (v == 0x3F800000u) fl = 1;
        else if (v > 1u) by = 1;
    }
    if (fl) atomicOr(&g_mask_float, 1);
    if (by) atomicOr(&g_mask_byte, 1);
}

__global__ void mask_to_bits(const void* __restrict__ mask, unsigned* __restrict__ bits)
{
    int idx = blockIdx.x * 256 + threadIdx.x;
    if (idx >= NQ * SW) return;
    int q = idx / SW, w = idx % SW;
    unsigned out = 0;
    int base = w * 32;
    int fl = g_mask_float, by = g_mask_byte;
    #pragma unroll 4
    for (int j = 0; j < 32; j++) {
        int s = base + j;
        if (s >= S_TOTAL) break;
        long off = (long)q * S_TOTAL + s;
        int blocked;
        if (fl)      blocked = ((const float*)mask)[off] != 0.f;
        else if (by) blocked = ((const unsigned char*)mask)[off] != 0;
        else         blocked = ((const int*)mask)[off] != 0;
        if (!blocked) out |= 1u << j;
    }
    bits[idx] = out;
}

__global__ void copy_out(const float* __restrict__ x, float* __restrict__ out, int n)
{
    int i = blockIdx.x * 256 + threadIdx.x;
    if (i < n) out[i] = x[i];
}

// ------------------------- host driver -------------------------
static inline dim3 gtile(int M, int N, int z, int BM) {
    return dim3((N + 63) / 64, (M + BM - 1) / BM, z);
}

extern "C" void kernel_launch(void* const* d_in, const int* in_sizes, int n_in,
                              void* d_out, int out_size)
{
    const float* srcs    = (const float*)d_in[0];
    const float* pos     = (const float*)d_in[1];
    const float* qemb    = (const float*)d_in[2];
    const void*  mask    = d_in[3];
    const float* sa_in_w = (const float*)d_in[4];
    const float* sa_in_b = (const float*)d_in[5];
    const float* sa_ow   = (const float*)d_in[6];
    const float* sa_ob   = (const float*)d_in[7];
    const float* ca_in_w = (const float*)d_in[8];
    const float* ca_in_b = (const float*)d_in[9];
    const float* ca_ow   = (const float*)d_in[10];
    const float* ca_ob   = (const float*)d_in[11];
    const float* ln1w = (const float*)d_in[12];
    const float* ln1b = (const float*)d_in[13];
    const float* ln2w = (const float*)d_in[14];
    const float* ln2b = (const float*)d_in[15];
    const float* ln3w = (const float*)d_in[16];
    const float* ln3b = (const float*)d_in[17];
    const float* ff1w = (const float*)d_in[18];
    const float* ff1b = (const float*)d_in[19];
    const float* ff2w = (const float*)d_in[20];
    const float* ff2b = (const float*)d_in[21];

    float *srct, *srcpos, *kvall, *opart, *x, *qe, *qkv, *qb, *ao, *t2, *ffh, *part;
    float2* mspart; unsigned *mbits, *ticket;
    cudaGetSymbolAddress((void**)&srct, g_srct);
    cudaGetSymbolAddress((void**)&srcpos, g_srcpos);
    cudaGetSymbolAddress((void**)&mbits, g_mbits);
    cudaGetSymbolAddress((void**)&kvall, g_kvall);
    cudaGetSymbolAddress((void**)&opart, g_opart);
    cudaGetSymbolAddress((void**)&mspart, g_mspart);
    cudaGetSymbolAddress((void**)&x, g_x);
    cudaGetSymbolAddress((void**)&qe, g_qe);
    cudaGetSymbolAddress((void**)&qkv, g_qkv);
    cudaGetSymbolAddress((void**)&qb, g_qb);
    cudaGetSymbolAddress((void**)&ao, g_ao);
    cudaGetSymbolAddress((void**)&t2, g_t2);
    cudaGetSymbolAddress((void**)&ffh, g_ffh);
    cudaGetSymbolAddress((void**)&part, g_part);
    cudaGetSymbolAddress((void**)&ticket, g_ticket);

    cudaFuncSetAttribute(flash_ca, cudaFuncAttributeMaxDynamicSharedMemorySize,
                         FLASH_SMEM_BYTES);

    const float scale = 0.17677669529663687f;  // 32^-0.5
    const int C = C_MODEL, S = S_TOTAL;
    const int BIG = 1 << 30;

    // Slot 4 (profiled): layer-0 SA QKV with KS=2 — direct A/B vs R12
    prep_src<<<dim3((S + 31) / 32, C / 32), dim3(32, 8)>>>(srcs, pos, srct, srcpos);
    init_qx<<<NQ, 256>>>(qemb, qe, x);
    detect_mask<<<1, 256>>>((const unsigned int*)mask);
    gemmbf<64><<<gtile(NQ, 3 * C, 2, 64), 256>>>(            // <- profiled slot
        x, x, qe, 512, sa_in_w, sa_in_b, qkv,
        NQ, 3 * C, C, C, C, 3 * C, 0, 0, 0, 0, scale, C, 0, 2, part, ticket);
    mask_to_bits<<<(NQ * SW + 255) / 256, 256>>>(mask, mbits);
    // KV projection: BM=64 for higher occupancy (4 CTAs/SM)
    gemmbf<64><<<gtile(S, 512, NLAYERS, 64), 256>>>(
        srcpos, srct, nullptr, 256,
        ca_in_w + C * C, ca_in_b + C, kvall,
        S, 512, C, C, C, 512,
        0L, (long)3 * C * C, (long)3 * C, (long)S * 512,
        1.f, 0, 0, 1, nullptr, nullptr);

    for (int l = 0; l < NLAYERS; l++) {
        const float* saw = sa_in_w + (long)l * 3 * C * C;
        const float* sab = sa_in_b + (long)l * 3 * C;
        const float* caw = ca_in_w + (long)l * 3 * C * C;
        const float* cab = ca_in_b + (long)l * 3 * C;
        const float* kvl = kvall + (long)l * S * 512;

        // ---- self attention ----
        if (l > 0) {
            gemmbf<64><<<gtile(NQ, 3 * C, 2, 64), 256>>>(
                x, x, qe, 512, saw, sab, qkv,
                NQ, 3 * C, C, C, C, 3 * C, 0, 0, 0, 0, scale, C, 0, 2, part, ticket);
        }
        sa_attn<<<dim3(NHEADS, (NQ + 7) / 8), 256>>>(qkv, ao);
        gemmbf<64><<<gtile(NQ, C, 4, 64), 256>>>(
            ao, nullptr, nullptr, BIG, sa_ow + (long)l * C * C, sa_ob + (long)l * C, t2,
            NQ, C, C, C, C, C, 0, 0, 0, 0, 1.f, 0, 0, 4, part, ticket);
        residual_ln<<<NQ, 256>>>(x, t2, ln2w + (long)l * C, ln2b + (long)l * C);

        // ---- cross attention (flash) ----
        gemmbf<64><<<gtile(NQ, C, 4, 64), 256>>>(
            x, nullptr, qe, BIG, caw, cab, qb,
            NQ, C, C, C, C, C, 0, 0, 0, 0, scale, C, 0, 4, part, ticket);
        flash_ca<<<dim3(NCHUNK, NHEADS), 320, FLASH_SMEM_BYTES>>>(
            qb, kvl, mbits, opart, mspart);
        ca_combine<<<(NHEADS * NQ * 4 + 255) / 256, 256>>>(opart, mspart, ao);
        gemmbf<64><<<gtile(NQ, C, 4, 64), 256>>>(
            ao, nullptr, nullptr, BIG, ca_ow + (long)l * C * C, ca_ob + (long)l * C, t2,
            NQ, C, C, C, C, C, 0, 0, 0, 0, 1.f, 0, 0, 4, part, ticket);
        residual_ln<<<NQ, 256>>>(x, t2, ln1w + (long)l * C, ln1b + (long)l * C);

        // ---- FFN ----
        gemmbf<64><<<gtile(NQ, DFF, 2, 64), 256>>>(
            x, nullptr, nullptr, BIG, ff1w + (long)l * DFF * C, ff1b + (long)l * DFF, ffh,
            NQ, DFF, C, C, C, DFF, 0, 0, 0, 0, 1.f, 0, 1, 2, part, ticket);
        gemmbf<64><<<gtile(NQ, C, 8, 64), 256>>>(
            ffh, nullptr, nullptr, BIG, ff2w + (long)l * C * DFF, ff2b + (long)l * C, t2,
            NQ, C, DFF, DFF, DFF, C, 0, 0, 0, 0, 1.f, 0, 0, 8, part, ticket);
        residual_ln<<<NQ, 256>>>(x, t2, ln3w + (long)l * C, ln3b + (long)l * C);
    }

    copy_out<<<(NQ * C + 255) / 256, 256>>>(x, (float*)d_out, NQ * C);
}

// round 14
// speedup vs baseline: 1.4044x; 1.4044x over previous
#include <cuda_runtime.h>
#include <cuda_bf16.h>

#define S_TOTAL 15768
#define NQ 300
#define C_MODEL 256
#define NHEADS 8
#define DHEAD 32
#define NLAYERS 6
#define DFF 1024
#define CHUNK 256
#define NCHUNK 62
#define SW 493
#define FLASH_SMEM_BYTES 65536

// ------------------------- scratch (device globals) -------------------------
__device__ float g_srct[S_TOTAL * C_MODEL];
__device__ float g_srcpos[S_TOTAL * C_MODEL];
__device__ unsigned g_mbits[NQ * SW];
__device__ float g_kvall[(size_t)NLAYERS * S_TOTAL * 512];
__device__ float g_opart[(size_t)NCHUNK * NHEADS * NQ * DHEAD];
__device__ float2 g_mspart[NCHUNK * NHEADS * NQ];
__device__ float g_x[NQ * C_MODEL];
__device__ float g_qe[NQ * C_MODEL];
__device__ float g_qkv[NQ * 3 * C_MODEL];
__device__ float g_qb[NQ * C_MODEL];
__device__ float g_ao[NQ * C_MODEL];
__device__ float g_t2[NQ * C_MODEL];
__device__ float g_ffh[NQ * DFF];
__device__ int   g_mask_float;
__device__ int   g_mask_byte;

// ------------------------- bf16x3 helpers -------------------------
__device__ __forceinline__ void split2(float x, float y, unsigned& hi, unsigned& lo)
{
    __nv_bfloat16 hx = __float2bfloat16(x);
    __nv_bfloat16 hy = __float2bfloat16(y);
    float rx = x - __bfloat162float(hx);
    float ry = y - __bfloat162float(hy);
    __nv_bfloat16 lx = __float2bfloat16(rx);
    __nv_bfloat16 ly = __float2bfloat16(ry);
    hi = (unsigned)__bfloat16_as_ushort(hx) | ((unsigned)__bfloat16_as_ushort(hy) << 16);
    lo = (unsigned)__bfloat16_as_ushort(lx) | ((unsigned)__bfloat16_as_ushort(ly) << 16);
}

__device__ __forceinline__ void mma16(float c[4], const unsigned a[4], const unsigned b[2])
{
    asm volatile(
        "mma.sync.aligned.m16n8k16.row.col.f32.bf16.bf16.f32 "
        "{%0,%1,%2,%3}, {%4,%5,%6,%7}, {%8,%9}, {%0,%1,%2,%3};"
        : "+f"(c[0]), "+f"(c[1]), "+f"(c[2]), "+f"(c[3])
        : "r"(a[0]), "r"(a[1]), "r"(a[2]), "r"(a[3]), "r"(b[0]), "r"(b[1]));
}

// ------------------------- pipelined, double-buffered bf16x3 GEMM -------------------------
// C[M,N] = act( alpha_col * (A[M,K] @ B[N,K]^T + bias[N]) )
// BM=64: double-buffered smem (one barrier/iter). BM=128: single buffer (48KB limit).
template <int BM>
__global__ __launch_bounds__(256) void gemmbf(
    const float* __restrict__ A0, const float* __restrict__ A1,
    const float* __restrict__ Aadd, int nsplit,
    const float* __restrict__ B, const float* __restrict__ bias,
    float* __restrict__ Cc, int M, int N, int K,
    int lda, int ldb, int ldc,
    long sA, long sB, long sbias, long sC,
    float alpha, int nscale, int relu)
{
    constexpr int BN = 64;
    constexpr int WMR = BM / 4;
    constexpr int MT = WMR / 16;
    constexpr int NT = 4;
    constexpr int NAROW = BM / 32;
    constexpr int NB = (BM == 64) ? 2 : 1;
    __shared__ unsigned Ah[NB][BM][17], Al[NB][BM][17];
    __shared__ unsigned Bh[NB][BN][17], Bl[NB][BN][17];

    int z = blockIdx.z;
    int m0 = blockIdx.y * BM, n0 = blockIdx.x * BN;
    const float* A = ((n0 >= nsplit) ? A1 : A0) + (long)z * sA;
    const float* Aa = (n0 < nsplit) ? Aadd : nullptr;
    const float* Bp = B + (long)z * sB;
    const float* bp = bias ? bias + (long)z * sbias : nullptr;
    float* Cp = Cc + (long)z * sC;

    int tid = threadIdx.x;
    int warp = tid >> 5, lane = tid & 31;
    int gid = lane >> 2, ctg = lane & 3;
    int wm = warp & 3, wn = warp >> 2;
    int mw = wm * WMR, nw = wn * 32;
    int lr = tid >> 3, lc4 = tid & 7;

    float acc[MT][NT][4] = {};
    float4 pa[NAROW], pb[2];

    // prefetch tile 0 (Aadd folded at load time)
    #pragma unroll
    for (int i = 0; i < NAROW; i++) {
        int row = i * 32 + lr;
        float4 v = make_float4(0.f, 0.f, 0.f, 0.f);
        if (m0 + row < M) {
            v = *(const float4*)&A[(long)(m0 + row) * lda + lc4 * 4];
            if (Aa) {
                float4 w = *(const float4*)&Aa[(long)(m0 + row) * lda + lc4 * 4];
                v.x += w.x; v.y += w.y; v.z += w.z; v.w += w.w;
            }
        }
        pa[i] = v;
    }
    #pragma unroll
    for (int i = 0; i < 2; i++) {
        int row = i * 32 + lr;
        pb[i] = make_float4(0.f, 0.f, 0.f, 0.f);
        if (n0 + row < N)
            pb[i] = *(const float4*)&Bp[(long)(n0 + row) * ldb + lc4 * 4];
    }

    int bsel = 0;
    for (int k0 = 0; k0 < K; k0 += 32) {
        if (NB == 1) __syncthreads();    // single-buffer: guard overwrite
        #pragma unroll
        for (int i = 0; i < NAROW; i++) {
            int row = i * 32 + lr;
            unsigned h0, l0, h1, l1;
            split2(pa[i].x, pa[i].y, h0, l0);
            split2(pa[i].z, pa[i].w, h1, l1);
            Ah[bsel][row][lc4 * 2] = h0;     Al[bsel][row][lc4 * 2] = l0;
            Ah[bsel][row][lc4 * 2 + 1] = h1; Al[bsel][row][lc4 * 2 + 1] = l1;
        }
        #pragma unroll
        for (int i = 0; i < 2; i++) {
            int row = i * 32 + lr;
            unsigned h0, l0, h1, l1;
            split2(pb[i].x, pb[i].y, h0, l0);
            split2(pb[i].z, pb[i].w, h1, l1);
            Bh[bsel][row][lc4 * 2] = h0;     Bl[bsel][row][lc4 * 2] = l0;
            Bh[bsel][row][lc4 * 2 + 1] = h1; Bl[bsel][row][lc4 * 2 + 1] = l1;
        }
        __syncthreads();

        // prefetch next tile while computing this one
        int kn = k0 + 32;
        if (kn < K) {
            #pragma unroll
            for (int i = 0; i < NAROW; i++) {
                int row = i * 32 + lr;
                float4 v = make_float4(0.f, 0.f, 0.f, 0.f);
                if (m0 + row < M) {
                    v = *(const float4*)&A[(long)(m0 + row) * lda + kn + lc4 * 4];
                    if (Aa) {
                        float4 w = *(const float4*)&Aa[(long)(m0 + row) * lda + kn + lc4 * 4];
                        v.x += w.x; v.y += w.y; v.z += w.z; v.w += w.w;
                    }
                }
                pa[i] = v;
            }
            #pragma unroll
            for (int i = 0; i < 2; i++) {
                int row = i * 32 + lr;
                float4 v = make_float4(0.f, 0.f, 0.f, 0.f);
                if (n0 + row < N)
                    v = *(const float4*)&Bp[(long)(n0 + row) * ldb + kn + lc4 * 4];
                pb[i] = v;
            }
        }

        #pragma unroll
        for (int st = 0; st < 2; st++) {
            int kc = st * 8;
            unsigned bh[NT][2], bl[NT][2];
            #pragma unroll
            for (int nt = 0; nt < NT; nt++) {
                int row = nw + nt * 8 + gid;
                bh[nt][0] = Bh[bsel][row][kc + ctg];
                bh[nt][1] = Bh[bsel][row][kc + ctg + 4];
                bl[nt][0] = Bl[bsel][row][kc + ctg];
                bl[nt][1] = Bl[bsel][row][kc + ctg + 4];
            }
            #pragma unroll
            for (int mt = 0; mt < MT; mt++) {
                int r0 = mw + mt * 16 + gid, r1 = r0 + 8;
                unsigned ah[4], al[4];
                ah[0] = Ah[bsel][r0][kc + ctg];     ah[1] = Ah[bsel][r1][kc + ctg];
                ah[2] = Ah[bsel][r0][kc + ctg + 4]; ah[3] = Ah[bsel][r1][kc + ctg + 4];
                al[0] = Al[bsel][r0][kc + ctg];     al[1] = Al[bsel][r1][kc + ctg];
                al[2] = Al[bsel][r0][kc + ctg + 4]; al[3] = Al[bsel][r1][kc + ctg + 4];
                #pragma unroll
                for (int nt = 0; nt < NT; nt++) {
                    mma16(acc[mt][nt], ah, bh[nt]);
                    mma16(acc[mt][nt], al, bh[nt]);
                    mma16(acc[mt][nt], ah, bl[nt]);
                }
            }
        }
        bsel ^= (NB - 1);
    }

    #pragma unroll
    for (int mt = 0; mt < MT; mt++) {
        #pragma unroll
        for (int nt = 0; nt < NT; nt++) {
            #pragma unroll
            for (int e = 0; e < 4; e++) {
                int m = m0 + mw + mt * 16 + gid + (e >> 1) * 8;
                int n = n0 + nw + nt * 8 + 2 * ctg + (e & 1);
                if (m >= M || n >= N) continue;
                float v = acc[mt][nt][e];
                if (bp) v += bp[n];
                if (n < nscale) v *= alpha;
                if (relu) v = fmaxf(v, 0.f);
                Cp[(long)m * ldc + n] = v;
            }
        }
    }
}

// ------------------------- residual + LayerNorm -------------------------
__global__ __launch_bounds__(256) void residual_ln(
    float* __restrict__ x, const float* __restrict__ res,
    const float* __restrict__ w, const float* __restrict__ b)
{
    int r = blockIdx.x;
    int c = threadIdx.x;
    float v = x[r * 256 + c] + res[r * 256 + c];
    __shared__ float red[256];
    red[c] = v; __syncthreads();
    for (int off = 128; off > 0; off >>= 1) { if (c < off) red[c] += red[c + off]; __syncthreads(); }
    float mean = red[0] * (1.f / 256.f);
    __syncthreads();
    float d = v - mean;
    red[c] = d * d; __syncthreads();
    for (int off = 128; off > 0; off >>= 1) { if (c < off) red[c] += red[c + off]; __syncthreads(); }
    float var = red[0] * (1.f / 256.f);
    x[r * 256 + c] = d * rsqrtf(var + 1e-5f) * w[c] + b[c];
}

// ------------------------- fused self-attention -------------------------
__global__ __launch_bounds__(256) void sa_attn(const float* __restrict__ qkv,
                                               float* __restrict__ ao)
{
    int h = blockIdx.x;
    int w = threadIdx.x >> 5;
    int lane = threadIdx.x & 31;
    int q = blockIdx.y * 8 + w;
    __shared__ float Qs[8][32];
    if (q < NQ) Qs[w][lane] = qkv[(long)q * 768 + h * 32 + lane];
    __syncwarp();
    if (q >= NQ) return;

    float m = -3.4e38f, s = 0.f, O[32] = {};
    for (int k = lane; k < NQ; k += 32) {
        const float4* Kp = (const float4*)&qkv[(long)k * 768 + 256 + h * 32];
        float d = 0.f;
        #pragma unroll
        for (int f = 0; f < 8; f++) {
            float4 kk = Kp[f];
            d += Qs[w][4*f]*kk.x + Qs[w][4*f+1]*kk.y + Qs[w][4*f+2]*kk.z + Qs[w][4*f+3]*kk.w;
        }
        float p;
        if (d > m) {
            float c = __expf(m - d);
            s = s * c + 1.f;
            #pragma unroll
            for (int i = 0; i < 32; i++) O[i] *= c;
            m = d; p = 1.f;
        } else { p = __expf(d - m); s += p; }
        const float4* Vp = (const float4*)&qkv[(long)k * 768 + 512 + h * 32];
        #pragma unroll
        for (int f = 0; f < 8; f++) {
            float4 vv = Vp[f];
            O[4*f]   += p * vv.x; O[4*f+1] += p * vv.y;
            O[4*f+2] += p * vv.z; O[4*f+3] += p * vv.w;
        }
    }
    float mg = m;
    #pragma unroll
    for (int o = 16; o; o >>= 1) mg = fmaxf(mg, __shfl_xor_sync(0xffffffffu, mg, o));
    float c = __expf(m - mg);
    s *= c;
    #pragma unroll
    for (int o = 16; o; o >>= 1) s += __shfl_xor_sync(0xffffffffu, s, o);
    float mine = 0.f;
    #pragma unroll
    for (int d = 0; d < 32; d++) {
        float v = O[d] * c;
        #pragma unroll
        for (int o = 16; o; o >>= 1) v += __shfl_xor_sync(0xffffffffu, v, o);
        if (lane == d) mine = v;
    }
    ao[(long)q * 256 + h * 32 + lane] = mine / s;
}

// ------------------------- flash cross-attention (per-lane bit walk, CHUNK=256) -------------------------
__global__ __launch_bounds__(320, 1) void flash_ca(
    const float* __restrict__ Qm,
    const float* __restrict__ KV,
    const unsigned* __restrict__ mbits,
    float* __restrict__ Opart, float2* __restrict__ MSpart)
{
    extern __shared__ __align__(16) float4 sh[];
    float4 (*Ks)[8] = (float4(*)[8])sh;
    float4 (*Vs)[8] = (float4(*)[8])(sh + CHUNK * 8);
    int ch = blockIdx.x, h = blockIdx.y;
    int s0 = ch * CHUNK;
    int nk = min(CHUNK, S_TOTAL - s0);
    int tid = threadIdx.x;
    for (int idx = tid; idx < nk * 8; idx += 320) {
        int j = idx >> 3, f = idx & 7;
        const float4* row = (const float4*)&KV[(long)(s0 + j) * 512];
        Ks[j][f] = row[h * 8 + f];
        Vs[j][f] = row[64 + h * 8 + f];
    }
    __syncthreads();

    int q = tid;
    if (q >= NQ) return;

    float Q[32], O[32] = {};
    #pragma unroll
    for (int f = 0; f < 8; f++)
        ((float4*)Q)[f] = *(const float4*)&Qm[(long)q * 256 + h * 32 + f * 4];
    float m = -3.4e38f, s = 0.f;

    for (int jw = 0; jw < nk; jw += 32) {
        unsigned w = mbits[q * SW + ((s0 + jw) >> 5)];
        while (w) {
            int jj = __ffs(w) - 1;
            w &= w - 1;
            int j = jw + jj;
            float d = 0.f;
            #pragma unroll
            for (int f = 0; f < 8; f++) {
                float4 kk = Ks[j][f];
                d += Q[4*f]*kk.x + Q[4*f+1]*kk.y + Q[4*f+2]*kk.z + Q[4*f+3]*kk.w;
            }
            float p;
            if (d > m) {
                float c = __expf(m - d);
                s = s * c + 1.f;
                #pragma unroll
                for (int i = 0; i < 32; i++) O[i] *= c;
                m = d; p = 1.f;
            } else { p = __expf(d - m); s += p; }
            #pragma unroll
            for (int f = 0; f < 8; f++) {
                float4 vv = Vs[j][f];
                O[4*f]   += p * vv.x; O[4*f+1] += p * vv.y;
                O[4*f+2] += p * vv.z; O[4*f+3] += p * vv.w;
            }
        }
    }
    long base = (long)(ch * NHEADS + h) * NQ + q;
    float4* op = (float4*)&Opart[base * DHEAD];
    #pragma unroll
    for (int f = 0; f < 8; f++) op[f] = ((float4*)O)[f];
    MSpart[base] = make_float2(m, s);
}

// ------------------------- combine (4-way split over head dim) -------------------------
__global__ void ca_combine(const float* __restrict__ Opart,
                           const float2* __restrict__ MSpart,
                           float* __restrict__ ao)
{
    int idx = blockIdx.x * blockDim.x + threadIdx.x;
    if (idx >= NHEADS * NQ * 4) return;
    int dg = idx & 3;
    int hq = idx >> 2;
    int h = hq / NQ, q = hq % NQ;
    float m = -3.4e38f, s = 0.f;
    float O[8] = {};
    for (int ch = 0; ch < NCHUNK; ch++) {
        long base = (long)(ch * NHEADS + h) * NQ + q;
        float2 ms = MSpart[base];
        if (ms.y <= 0.f) continue;
        float c2;
        if (ms.x > m) {
            float c = (m > -3.0e38f) ? __expf(m - ms.x) : 0.f;
            s *= c;
            #pragma unroll
            for (int d = 0; d < 8; d++) O[d] *= c;
            m = ms.x;
            c2 = 1.f;
        } else {
            c2 = __expf(ms.x - m);
        }
        s += ms.y * c2;
        const float4* op = (const float4*)&Opart[base * DHEAD + dg * 8];
        float4 v0 = op[0], v1 = op[1];
        O[0] += c2 * v0.x; O[1] += c2 * v0.y; O[2] += c2 * v0.z; O[3] += c2 * v0.w;
        O[4] += c2 * v1.x; O[5] += c2 * v1.y; O[6] += c2 * v1.z; O[7] += c2 * v1.w;
    }
    float inv = 1.f / s;
    float4* outp = (float4*)&ao[(long)q * 256 + h * 32 + dg * 8];
    outp[0] = make_float4(O[0] * inv, O[1] * inv, O[2] * inv, O[3] * inv);
    outp[1] = make_float4(O[4] * inv, O[5] * inv, O[6] * inv, O[7] * inv);
}

// ------------------------- small kernels -------------------------
__global__ void prep_src(const float* __restrict__ srcs, const float* __restrict__ pos,
                         float* __restrict__ srct, float* __restrict__ srcpos)
{
    __shared__ float t1[32][33], t2[32][33];
    int s0 = blockIdx.x * 32, c0 = blockIdx.y * 32;
    int tx = threadIdx.x, ty = threadIdx.y;
    #pragma unroll
    for (int i = 0; i < 4; i++) {
        int c = c0 + ty + i * 8, s = s0 + tx;
        float a = 0.f, f = 0.f;
        if (s < S_TOTAL) { a = srcs[(long)c * S_TOTAL + s]; f = pos[(long)c * S_TOTAL + s]; }
        t1[ty + i * 8][tx] = a;
        t2[ty + i * 8][tx] = f;
    }
    __syncthreads();
    #pragma unroll
    for (int i = 0; i < 4; i++) {
        int s = s0 + ty + i * 8, c = c0 + tx;
        if (s < S_TOTAL) {
            float a = t1[tx][ty + i * 8];
            float f = t2[tx][ty + i * 8];
            srct[(long)s * 256 + c]   = a;
            srcpos[(long)s * 256 + c] = a + f;
        }
    }
}

__global__ void init_qx(const float* __restrict__ qemb, float* __restrict__ qe, float* __restrict__ x)
{
    int r = blockIdx.x, c = threadIdx.x;
    qe[r * 256 + c] = qemb[r * 512 + c];
    x[r * 256 + c]  = qemb[r * 512 + 256 + c];
}

__global__ void detect_mask(const unsigned int* __restrict__ w)
{
    if (threadIdx.x == 0) { g_mask_float = 0; g_mask_byte = 0; }
    __syncthreads();
    int fl = 0, by = 0;
    for (int i = threadIdx.x; i < 65536; i += 256) {
        unsigned int v = w[i];
        if (v == 0x3F800000u) fl = 1;
        else if (v > 1u) by = 1;
    }
    if (fl) atomicOr(&g_mask_float, 1);
    if (by) atomicOr(&g_mask_byte, 1);
}

__global__ void mask_to_bits(const void* __restrict__ mask, unsigned* __restrict__ bits)
{
    int idx = blockIdx.x * 256 + threadIdx.x;
    if (idx >= NQ * SW) return;
    int q = idx / SW, w = idx % SW;
    unsigned out = 0;
    int base = w * 32;
    int fl = g_mask_float, by = g_mask_byte;
    #pragma unroll 4
    for (int j = 0; j < 32; j++) {
        int s = base + j;
        if (s >= S_TOTAL) break;
        long off = (long)q * S_TOTAL + s;
        int blocked;
        if (fl)      blocked = ((const float*)mask)[off] != 0.f;
        else if (by) blocked = ((const unsigned char*)mask)[off] != 0;
        else         blocked = ((const int*)mask)[off] != 0;
        if (!blocked) out |= 1u << j;
    }
    bits[idx] = out;
}

__global__ void copy_out(const float* __restrict__ x, float* __restrict__ out, int n)
{
    int i = blockIdx.x * 256 + threadIdx.x;
    if (i < n) out[i] = x[i];
}

// ------------------------- host driver -------------------------
static inline dim3 gtile(int M, int N, int z, int BM) {
    return dim3((N + 63) / 64, (M + BM - 1) / BM, z);
}

extern "C" void kernel_launch(void* const* d_in, const int* in_sizes, int n_in,
                              void* d_out, int out_size)
{
    const float* srcs    = (const float*)d_in[0];
    const float* pos     = (const float*)d_in[1];
    const float* qemb    = (const float*)d_in[2];
    const void*  mask    = d_in[3];
    const float* sa_in_w = (const float*)d_in[4];
    const float* sa_in_b = (const float*)d_in[5];
    const float* sa_ow   = (const float*)d_in[6];
    const float* sa_ob   = (const float*)d_in[7];
    const float* ca_in_w = (const float*)d_in[8];
    const float* ca_in_b = (const float*)d_in[9];
    const float* ca_ow   = (const float*)d_in[10];
    const float* ca_ob   = (const float*)d_in[11];
    const float* ln1w = (const float*)d_in[12];
    const float* ln1b = (const float*)d_in[13];
    const float* ln2w = (const float*)d_in[14];
    const float* ln2b = (const float*)d_in[15];
    const float* ln3w = (const float*)d_in[16];
    const float* ln3b = (const float*)d_in[17];
    const float* ff1w = (const float*)d_in[18];
    const float* ff1b = (const float*)d_in[19];
    const float* ff2w = (const float*)d_in[20];
    const float* ff2b = (const float*)d_in[21];

    float *srct, *srcpos, *kvall, *opart, *x, *qe, *qkv, *qb, *ao, *t2, *ffh;
    float2* mspart; unsigned* mbits;
    cudaGetSymbolAddress((void**)&srct, g_srct);
    cudaGetSymbolAddress((void**)&srcpos, g_srcpos);
    cudaGetSymbolAddress((void**)&mbits, g_mbits);
    cudaGetSymbolAddress((void**)&kvall, g_kvall);
    cudaGetSymbolAddress((void**)&opart, g_opart);
    cudaGetSymbolAddress((void**)&mspart, g_mspart);
    cudaGetSymbolAddress((void**)&x, g_x);
    cudaGetSymbolAddress((void**)&qe, g_qe);
    cudaGetSymbolAddress((void**)&qkv, g_qkv);
    cudaGetSymbolAddress((void**)&qb, g_qb);
    cudaGetSymbolAddress((void**)&ao, g_ao);
    cudaGetSymbolAddress((void**)&t2, g_t2);
    cudaGetSymbolAddress((void**)&ffh, g_ffh);

    cudaFuncSetAttribute(flash_ca, cudaFuncAttributeMaxDynamicSharedMemorySize,
                         FLASH_SMEM_BYTES);

    const float scale = 0.17677669529663687f;  // 32^-0.5
    const int C = C_MODEL, S = S_TOTAL;
    const int BIG = 1 << 30;

    // Slot 4 (profiled): layer-0 SA QKV — A/B of double-buffered gemmbf<64>
    prep_src<<<dim3((S + 31) / 32, C / 32), dim3(32, 8)>>>(srcs, pos, srct, srcpos);
    init_qx<<<NQ, 256>>>(qemb, qe, x);
    detect_mask<<<1, 256>>>((const unsigned int*)mask);
    gemmbf<64><<<gtile(NQ, 3 * C, 1, 64), 256>>>(            // <- profiled slot
        x, x, qe, 512, sa_in_w, sa_in_b, qkv,
        NQ, 3 * C, C, C, C, 3 * C, 0, 0, 0, 0, scale, C, 0);
    mask_to_bits<<<(NQ * SW + 255) / 256, 256>>>(mask, mbits);
    gemmbf<128><<<gtile(S, 512, NLAYERS, 128), 256>>>(
        srcpos, srct, nullptr, 256,
        ca_in_w + C * C, ca_in_b + C, kvall,
        S, 512, C, C, C, 512,
        0L, (long)3 * C * C, (long)3 * C, (long)S * 512,
        1.f, 0, 0);

    for (int l = 0; l < NLAYERS; l++) {
        const float* saw = sa_in_w + (long)l * 3 * C * C;
        const float* sab = sa_in_b + (long)l * 3 * C;
        const float* caw = ca_in_w + (long)l * 3 * C * C;
        const float* cab = ca_in_b + (long)l * 3 * C;
        const float* kvl = kvall + (long)l * S * 512;

        // ---- self attention ----
        if (l > 0) {
            gemmbf<64><<<gtile(NQ, 3 * C, 1, 64), 256>>>(
                x, x, qe, 512, saw, sab, qkv,
                NQ, 3 * C, C, C, C, 3 * C, 0, 0, 0, 0, scale, C, 0);
        }
        sa_attn<<<dim3(NHEADS, (NQ + 7) / 8), 256>>>(qkv, ao);
        gemmbf<64><<<gtile(NQ, C, 1, 64), 256>>>(
            ao, nullptr, nullptr, BIG, sa_ow + (long)l * C * C, sa_ob + (long)l * C, t2,
            NQ, C, C, C, C, C, 0, 0, 0, 0, 1.f, 0, 0);
        residual_ln<<<NQ, 256>>>(x, t2, ln2w + (long)l * C, ln2b + (long)l * C);

        // ---- cross attention (flash) ----
        gemmbf<64><<<gtile(NQ, C, 1, 64), 256>>>(
            x, nullptr, qe, BIG, caw, cab, qb,
            NQ, C, C, C, C, C, 0, 0, 0, 0, scale, C, 0);
        flash_ca<<<dim3(NCHUNK, NHEADS), 320, FLASH_SMEM_BYTES>>>(
            qb, kvl, mbits, opart, mspart);
        ca_combine<<<(NHEADS * NQ * 4 + 255) / 256, 256>>>(opart, mspart, ao);
        gemmbf<64><<<gtile(NQ, C, 1, 64), 256>>>(
            ao, nullptr, nullptr, BIG, ca_ow + (long)l * C * C, ca_ob + (long)l * C, t2,
            NQ, C, C, C, C, C, 0, 0, 0, 0, 1.f, 0, 0);
        residual_ln<<<NQ, 256>>>(x, t2, ln1w + (long)l * C, ln1b + (long)l * C);

        // ---- FFN ----
        gemmbf<64><<<gtile(NQ, DFF, 1, 64), 256>>>(
            x, nullptr, nullptr, BIG, ff1w + (long)l * DFF * C, ff1b + (long)l * DFF, ffh,
            NQ, DFF, C, C, C, DFF, 0, 0, 0, 0, 1.f, 0, 1);
        gemmbf<64><<<gtile(NQ, C, 1, 64), 256>>>(
            ffh, nullptr, nullptr, BIG, ff2w + (long)l * C * DFF, ff2b + (long)l * C, t2,
            NQ, C, DFF, DFF, DFF, C, 0, 0, 0, 0, 1.f, 0, 0);
        residual_ln<<<NQ, 256>>>(x, t2, ln3w + (long)l * C, ln3b + (long)l * C);
    }

    copy_out<<<(NQ * C + 255) / 256, 256>>>(x, (float*)d_out, NQ * C);
}

// round 15
// speedup vs baseline: 1.4406x; 1.0258x over previous
#include <cuda_runtime.h>
#include <cuda_bf16.h>

#define S_TOTAL 15768
#define NQ 300
#define C_MODEL 256
#define NHEADS 8
#define DHEAD 32
#define NLAYERS 6
#define DFF 1024
#define CHUNK 256
#define NCHUNK 62
#define SW 493
#define FLASH_SMEM_BYTES 65536
#define PAD 20   // smem row stride in words; conflict-free for (gid,ctg) fragment loads

// ------------------------- scratch (device globals) -------------------------
__device__ float g_srct[S_TOTAL * C_MODEL];
__device__ float g_srcpos[S_TOTAL * C_MODEL];
__device__ unsigned g_mbits[NQ * SW];
__device__ float g_kvall[(size_t)NLAYERS * S_TOTAL * 512];
__device__ float g_opart[(size_t)NCHUNK * NHEADS * NQ * DHEAD];
__device__ float2 g_mspart[NCHUNK * NHEADS * NQ];
__device__ float g_x[NQ * C_MODEL];
__device__ float g_qe[NQ * C_MODEL];
__device__ float g_qkv[NQ * 3 * C_MODEL];
__device__ float g_qb[NQ * C_MODEL];
__device__ float g_ao[NQ * C_MODEL];
__device__ float g_t2[NQ * C_MODEL];
__device__ float g_ffh[NQ * DFF];
__device__ int   g_mask_float;
__device__ int   g_mask_byte;

// ------------------------- bf16x3 helpers -------------------------
__device__ __forceinline__ void split2(float x, float y, unsigned& hi, unsigned& lo)
{
    __nv_bfloat16 hx = __float2bfloat16(x);
    __nv_bfloat16 hy = __float2bfloat16(y);
    float rx = x - __bfloat162float(hx);
    float ry = y - __bfloat162float(hy);
    __nv_bfloat16 lx = __float2bfloat16(rx);
    __nv_bfloat16 ly = __float2bfloat16(ry);
    hi = (unsigned)__bfloat16_as_ushort(hx) | ((unsigned)__bfloat16_as_ushort(hy) << 16);
    lo = (unsigned)__bfloat16_as_ushort(lx) | ((unsigned)__bfloat16_as_ushort(ly) << 16);
}

__device__ __forceinline__ void mma16(float c[4], const unsigned a[4], const unsigned b[2])
{
    asm volatile(
        "mma.sync.aligned.m16n8k16.row.col.f32.bf16.bf16.f32 "
        "{%0,%1,%2,%3}, {%4,%5,%6,%7}, {%8,%9}, {%0,%1,%2,%3};"
        : "+f"(c[0]), "+f"(c[1]), "+f"(c[2]), "+f"(c[3])
        : "r"(a[0]), "r"(a[1]), "r"(a[2]), "r"(a[3]), "r"(b[0]), "r"(b[1]));
}

// ------------------------- pipelined, double-buffered bf16x3 GEMM -------------------------
// C[M,N] = act( alpha_col * (A[M,K] @ B[N,K]^T + bias[N]) )
// BM=64: double-buffered smem. BM=128: single buffer. PAD=20 -> conflict-free fragment LDS.
template <int BM>
__global__ __launch_bounds__(256) void gemmbf(
    const float* __restrict__ A0, const float* __restrict__ A1,
    const float* __restrict__ Aadd, int nsplit,
    const float* __restrict__ B, const float* __restrict__ bias,
    float* __restrict__ Cc, int M, int N, int K,
    int lda, int ldb, int ldc,
    long sA, long sB, long sbias, long sC,
    float alpha, int nscale, int relu)
{
    constexpr int BN = 64;
    constexpr int WMR = BM / 4;
    constexpr int MT = WMR / 16;
    constexpr int NT = 4;
    constexpr int NAROW = BM / 32;
    constexpr int NB = (BM == 64) ? 2 : 1;
    __shared__ unsigned Ah[NB][BM][PAD], Al[NB][BM][PAD];
    __shared__ unsigned Bh[NB][BN][PAD], Bl[NB][BN][PAD];

    int z = blockIdx.z;
    int m0 = blockIdx.y * BM, n0 = blockIdx.x * BN;
    const float* A = ((n0 >= nsplit) ? A1 : A0) + (long)z * sA;
    const float* Aa = (n0 < nsplit) ? Aadd : nullptr;
    const float* Bp = B + (long)z * sB;
    const float* bp = bias ? bias + (long)z * sbias : nullptr;
    float* Cp = Cc + (long)z * sC;

    int tid = threadIdx.x;
    int warp = tid >> 5, lane = tid & 31;
    int gid = lane >> 2, ctg = lane & 3;
    int wm = warp & 3, wn = warp >> 2;
    int mw = wm * WMR, nw = wn * 32;
    int lr = tid >> 3, lc4 = tid & 7;

    float acc[MT][NT][4] = {};
    float4 pa[NAROW], pb[2];

    // prefetch tile 0 (Aadd folded at load time)
    #pragma unroll
    for (int i = 0; i < NAROW; i++) {
        int row = i * 32 + lr;
        float4 v = make_float4(0.f, 0.f, 0.f, 0.f);
        if (m0 + row < M) {
            v = *(const float4*)&A[(long)(m0 + row) * lda + lc4 * 4];
            if (Aa) {
                float4 w = *(const float4*)&Aa[(long)(m0 + row) * lda + lc4 * 4];
                v.x += w.x; v.y += w.y; v.z += w.z; v.w += w.w;
            }
        }
        pa[i] = v;
    }
    #pragma unroll
    for (int i = 0; i < 2; i++) {
        int row = i * 32 + lr;
        pb[i] = make_float4(0.f, 0.f, 0.f, 0.f);
        if (n0 + row < N)
            pb[i] = *(const float4*)&Bp[(long)(n0 + row) * ldb + lc4 * 4];
    }

    int bsel = 0;
    for (int k0 = 0; k0 < K; k0 += 32) {
        if (NB == 1) __syncthreads();    // single-buffer: guard overwrite
        #pragma unroll
        for (int i = 0; i < NAROW; i++) {
            int row = i * 32 + lr;
            unsigned h0, l0, h1, l1;
            split2(pa[i].x, pa[i].y, h0, l0);
            split2(pa[i].z, pa[i].w, h1, l1);
            Ah[bsel][row][lc4 * 2] = h0;     Al[bsel][row][lc4 * 2] = l0;
            Ah[bsel][row][lc4 * 2 + 1] = h1; Al[bsel][row][lc4 * 2 + 1] = l1;
        }
        #pragma unroll
        for (int i = 0; i < 2; i++) {
            int row = i * 32 + lr;
            unsigned h0, l0, h1, l1;
            split2(pb[i].x, pb[i].y, h0, l0);
            split2(pb[i].z, pb[i].w, h1, l1);
            Bh[bsel][row][lc4 * 2] = h0;     Bl[bsel][row][lc4 * 2] = l0;
            Bh[bsel][row][lc4 * 2 + 1] = h1; Bl[bsel][row][lc4 * 2 + 1] = l1;
        }
        __syncthreads();

        // prefetch next tile while computing this one
        int kn = k0 + 32;
        if (kn < K) {
            #pragma unroll
            for (int i = 0; i < NAROW; i++) {
                int row = i * 32 + lr;
                float4 v = make_float4(0.f, 0.f, 0.f, 0.f);
                if (m0 + row < M) {
                    v = *(const float4*)&A[(long)(m0 + row) * lda + kn + lc4 * 4];
                    if (Aa) {
                        float4 w = *(const float4*)&Aa[(long)(m0 + row) * lda + kn + lc4 * 4];
                        v.x += w.x; v.y += w.y; v.z += w.z; v.w += w.w;
                    }
                }
                pa[i] = v;
            }
            #pragma unroll
            for (int i = 0; i < 2; i++) {
                int row = i * 32 + lr;
                float4 v = make_float4(0.f, 0.f, 0.f, 0.f);
                if (n0 + row < N)
                    v = *(const float4*)&Bp[(long)(n0 + row) * ldb + kn + lc4 * 4];
                pb[i] = v;
            }
        }

        #pragma unroll
        for (int st = 0; st < 2; st++) {
            int kc = st * 8;
            unsigned bh[NT][2], bl[NT][2];
            #pragma unroll
            for (int nt = 0; nt < NT; nt++) {
                int row = nw + nt * 8 + gid;
                bh[nt][0] = Bh[bsel][row][kc + ctg];
                bh[nt][1] = Bh[bsel][row][kc + ctg + 4];
                bl[nt][0] = Bl[bsel][row][kc + ctg];
                bl[nt][1] = Bl[bsel][row][kc + ctg + 4];
            }
            #pragma unroll
            for (int mt = 0; mt < MT; mt++) {
                int r0 = mw + mt * 16 + gid, r1 = r0 + 8;
                unsigned ah[4], al[4];
                ah[0] = Ah[bsel][r0][kc + ctg];     ah[1] = Ah[bsel][r1][kc + ctg];
                ah[2] = Ah[bsel][r0][kc + ctg + 4]; ah[3] = Ah[bsel][r1][kc + ctg + 4];
                al[0] = Al[bsel][r0][kc + ctg];     al[1] = Al[bsel][r1][kc + ctg];
                al[2] = Al[bsel][r0][kc + ctg + 4]; al[3] = Al[bsel][r1][kc + ctg + 4];
                #pragma unroll
                for (int nt = 0; nt < NT; nt++) {
                    mma16(acc[mt][nt], ah, bh[nt]);
                    mma16(acc[mt][nt], al, bh[nt]);
                    mma16(acc[mt][nt], ah, bl[nt]);
                }
            }
        }
        bsel ^= (NB - 1);
    }

    #pragma unroll
    for (int mt = 0; mt < MT; mt++) {
        #pragma unroll
        for (int nt = 0; nt < NT; nt++) {
            #pragma unroll
            for (int e = 0; e < 4; e++) {
                int m = m0 + mw + mt * 16 + gid + (e >> 1) * 8;
                int n = n0 + nw + nt * 8 + 2 * ctg + (e & 1);
                if (m >= M || n >= N) continue;
                float v = acc[mt][nt][e];
                if (bp) v += bp[n];
                if (n < nscale) v *= alpha;
                if (relu) v = fmaxf(v, 0.f);
                Cp[(long)m * ldc + n] = v;
            }
        }
    }
}

// ------------------------- residual + LayerNorm -------------------------
__global__ __launch_bounds__(256) void residual_ln(
    float* __restrict__ x, const float* __restrict__ res,
    const float* __restrict__ w, const float* __restrict__ b)
{
    int r = blockIdx.x;
    int c = threadIdx.x;
    float v = x[r * 256 + c] + res[r * 256 + c];
    __shared__ float red[256];
    red[c] = v; __syncthreads();
    for (int off = 128; off > 0; off >>= 1) { if (c < off) red[c] += red[c + off]; __syncthreads(); }
    float mean = red[0] * (1.f / 256.f);
    __syncthreads();
    float d = v - mean;
    red[c] = d * d; __syncthreads();
    for (int off = 128; off > 0; off >>= 1) { if (c < off) red[c] += red[c + off]; __syncthreads(); }
    float var = red[0] * (1.f / 256.f);
    x[r * 256 + c] = d * rsqrtf(var + 1e-5f) * w[c] + b[c];
}

// ------------------------- fused self-attention -------------------------
__global__ __launch_bounds__(256) void sa_attn(const float* __restrict__ qkv,
                                               float* __restrict__ ao)
{
    int h = blockIdx.x;
    int w = threadIdx.x >> 5;
    int lane = threadIdx.x & 31;
    int q = blockIdx.y * 8 + w;
    __shared__ float Qs[8][32];
    if (q < NQ) Qs[w][lane] = qkv[(long)q * 768 + h * 32 + lane];
    __syncwarp();
    if (q >= NQ) return;

    float m = -3.4e38f, s = 0.f, O[32] = {};
    for (int k = lane; k < NQ; k += 32) {
        const float4* Kp = (const float4*)&qkv[(long)k * 768 + 256 + h * 32];
        float d = 0.f;
        #pragma unroll
        for (int f = 0; f < 8; f++) {
            float4 kk = Kp[f];
            d += Qs[w][4*f]*kk.x + Qs[w][4*f+1]*kk.y + Qs[w][4*f+2]*kk.z + Qs[w][4*f+3]*kk.w;
        }
        float p;
        if (d > m) {
            float c = __expf(m - d);
            s = s * c + 1.f;
            #pragma unroll
            for (int i = 0; i < 32; i++) O[i] *= c;
            m = d; p = 1.f;
        } else { p = __expf(d - m); s += p; }
        const float4* Vp = (const float4*)&qkv[(long)k * 768 + 512 + h * 32];
        #pragma unroll
        for (int f = 0; f < 8; f++) {
            float4 vv = Vp[f];
            O[4*f]   += p * vv.x; O[4*f+1] += p * vv.y;
            O[4*f+2] += p * vv.z; O[4*f+3] += p * vv.w;
        }
    }
    float mg = m;
    #pragma unroll
    for (int o = 16; o; o >>= 1) mg = fmaxf(mg, __shfl_xor_sync(0xffffffffu, mg, o));
    float c = __expf(m - mg);
    s *= c;
    #pragma unroll
    for (int o = 16; o; o >>= 1) s += __shfl_xor_sync(0xffffffffu, s, o);
    float mine = 0.f;
    #pragma unroll
    for (int d = 0; d < 32; d++) {
        float v = O[d] * c;
        #pragma unroll
        for (int o = 16; o; o >>= 1) v += __shfl_xor_sync(0xffffffffu, v, o);
        if (lane == d) mine = v;
    }
    ao[(long)q * 256 + h * 32 + lane] = mine / s;
}

// ------------------------- flash cross-attention (per-lane bit walk, CHUNK=256) -------------------------
__global__ __launch_bounds__(320, 1) void flash_ca(
    const float* __restrict__ Qm,
    const float* __restrict__ KV,
    const unsigned* __restrict__ mbits,
    float* __restrict__ Opart, float2* __restrict__ MSpart)
{
    extern __shared__ __align__(16) float4 sh[];
    float4 (*Ks)[8] = (float4(*)[8])sh;
    float4 (*Vs)[8] = (float4(*)[8])(sh + CHUNK * 8);
    int ch = blockIdx.x, h = blockIdx.y;
    int s0 = ch * CHUNK;
    int nk = min(CHUNK, S_TOTAL - s0);
    int tid = threadIdx.x;
    for (int idx = tid; idx < nk * 8; idx += 320) {
        int j = idx >> 3, f = idx & 7;
        const float4* row = (const float4*)&KV[(long)(s0 + j) * 512];
        Ks[j][f] = row[h * 8 + f];
        Vs[j][f] = row[64 + h * 8 + f];
    }
    __syncthreads();

    int q = tid;
    if (q >= NQ) return;

    float Q[32], O[32] = {};
    #pragma unroll
    for (int f = 0; f < 8; f++)
        ((float4*)Q)[f] = *(const float4*)&Qm[(long)q * 256 + h * 32 + f * 4];
    float m = -3.4e38f, s = 0.f;

    for (int jw = 0; jw < nk; jw += 32) {
        unsigned w = mbits[q * SW + ((s0 + jw) >> 5)];
        while (w) {
            int jj = __ffs(w) - 1;
            w &= w - 1;
            int j = jw + jj;
            float d = 0.f;
            #pragma unroll
            for (int f = 0; f < 8; f++) {
                float4 kk = Ks[j][f];
                d += Q[4*f]*kk.x + Q[4*f+1]*kk.y + Q[4*f+2]*kk.z + Q[4*f+3]*kk.w;
            }
            float p;
            if (d > m) {
                float c = __expf(m - d);
                s = s * c + 1.f;
                #pragma unroll
                for (int i = 0; i < 32; i++) O[i] *= c;
                m = d; p = 1.f;
            } else { p = __expf(d - m); s += p; }
            #pragma unroll
            for (int f = 0; f < 8; f++) {
                float4 vv = Vs[j][f];
                O[4*f]   += p * vv.x; O[4*f+1] += p * vv.y;
                O[4*f+2] += p * vv.z; O[4*f+3] += p * vv.w;
            }
        }
    }
    long base = (long)(ch * NHEADS + h) * NQ + q;
    float4* op = (float4*)&Opart[base * DHEAD];
    #pragma unroll
    for (int f = 0; f < 8; f++) op[f] = ((float4*)O)[f];
    MSpart[base] = make_float2(m, s);
}

// ------------------------- combine (4-way split over head dim) -------------------------
__global__ void ca_combine(const float* __restrict__ Opart,
                           const float2* __restrict__ MSpart,
                           float* __restrict__ ao)
{
    int idx = blockIdx.x * blockDim.x + threadIdx.x;
    if (idx >= NHEADS * NQ * 4) return;
    int dg = idx & 3;
    int hq = idx >> 2;
    int h = hq / NQ, q = hq % NQ;
    float m = -3.4e38f, s = 0.f;
    float O[8] = {};
    for (int ch = 0; ch < NCHUNK; ch++) {
        long base = (long)(ch * NHEADS + h) * NQ + q;
        float2 ms = MSpart[base];
        if (ms.y <= 0.f) continue;
        float c2;
        if (ms.x > m) {
            float c = (m > -3.0e38f) ? __expf(m - ms.x) : 0.f;
            s *= c;
            #pragma unroll
            for (int d = 0; d < 8; d++) O[d] *= c;
            m = ms.x;
            c2 = 1.f;
        } else {
            c2 = __expf(ms.x - m);
        }
        s += ms.y * c2;
        const float4* op = (const float4*)&Opart[base * DHEAD + dg * 8];
        float4 v0 = op[0], v1 = op[1];
        O[0] += c2 * v0.x; O[1] += c2 * v0.y; O[2] += c2 * v0.z; O[3] += c2 * v0.w;
        O[4] += c2 * v1.x; O[5] += c2 * v1.y; O[6] += c2 * v1.z; O[7] += c2 * v1.w;
    }
    float inv = 1.f / s;
    float4* outp = (float4*)&ao[(long)q * 256 + h * 32 + dg * 8];
    outp[0] = make_float4(O[0] * inv, O[1] * inv, O[2] * inv, O[3] * inv);
    outp[1] = make_float4(O[4] * inv, O[5] * inv, O[6] * inv, O[7] * inv);
}

// ------------------------- small kernels -------------------------
__global__ void prep_src(const float* __restrict__ srcs, const float* __restrict__ pos,
                         float* __restrict__ srct, float* __restrict__ srcpos)
{
    __shared__ float t1[32][33], t2[32][33];
    int s0 = blockIdx.x * 32, c0 = blockIdx.y * 32;
    int tx = threadIdx.x, ty = threadIdx.y;
    #pragma unroll
    for (int i = 0; i < 4; i++) {
        int c = c0 + ty + i * 8, s = s0 + tx;
        float a = 0.f, f = 0.f;
        if (s < S_TOTAL) { a = srcs[(long)c * S_TOTAL + s]; f = pos[(long)c * S_TOTAL + s]; }
        t1[ty + i * 8][tx] = a;
        t2[ty + i * 8][tx] = f;
    }
    __syncthreads();
    #pragma unroll
    for (int i = 0; i < 4; i++) {
        int s = s0 + ty + i * 8, c = c0 + tx;
        if (s < S_TOTAL) {
            float a = t1[tx][ty + i * 8];
            float f = t2[tx][ty + i * 8];
            srct[(long)s * 256 + c]   = a;
            srcpos[(long)s * 256 + c] = a + f;
        }
    }
}

__global__ void init_qx(const float* __restrict__ qemb, float* __restrict__ qe, float* __restrict__ x)
{
    int r = blockIdx.x, c = threadIdx.x;
    qe[r * 256 + c] = qemb[r * 512 + c];
    x[r * 256 + c]  = qemb[r * 512 + 256 + c];
}

__global__ void detect_mask(const unsigned int* __restrict__ w)
{
    if (threadIdx.x == 0) { g_mask_float = 0; g_mask_byte = 0; }
    __syncthreads();
    int fl = 0, by = 0;
    for (int i = threadIdx.x; i < 65536; i += 256) {
        unsigned int v = w[i];
        if (v == 0x3F800000u) fl = 1;
        else if (v > 1u) by = 1;
    }
    if (fl) atomicOr(&g_mask_float, 1);
    if (by) atomicOr(&g_mask_byte, 1);
}

__global__ void mask_to_bits(const void* __restrict__ mask, unsigned* __restrict__ bits)
{
    int idx = blockIdx.x * 256 + threadIdx.x;
    if (idx >= NQ * SW) return;
    int q = idx / SW, w = idx % SW;
    unsigned out = 0;
    int base = w * 32;
    int fl = g_mask_float, by = g_mask_byte;
    #pragma unroll 4
    for (int j = 0; j < 32; j++) {
        int s = base + j;
        if (s >= S_TOTAL) break;
        long off = (long)q * S_TOTAL + s;
        int blocked;
        if (fl)      blocked = ((const float*)mask)[off] != 0.f;
        else if (by) blocked = ((const unsigned char*)mask)[off] != 0;
        else         blocked = ((const int*)mask)[off] != 0;
        if (!blocked) out |= 1u << j;
    }
    bits[idx] = out;
}

__global__ void copy_out(const float* __restrict__ x, float* __restrict__ out, int n)
{
    int i = blockIdx.x * 256 + threadIdx.x;
    if (i < n) out[i] = x[i];
}

// ------------------------- host driver -------------------------
static inline dim3 gtile(int M, int N, int z, int BM) {
    return dim3((N + 63) / 64, (M + BM - 1) / BM, z);
}

extern "C" void kernel_launch(void* const* d_in, const int* in_sizes, int n_in,
                              void* d_out, int out_size)
{
    const float* srcs    = (const float*)d_in[0];
    const float* pos     = (const float*)d_in[1];
    const float* qemb    = (const float*)d_in[2];
    const void*  mask    = d_in[3];
    const float* sa_in_w = (const float*)d_in[4];
    const float* sa_in_b = (const float*)d_in[5];
    const float* sa_ow   = (const float*)d_in[6];
    const float* sa_ob   = (const float*)d_in[7];
    const float* ca_in_w = (const float*)d_in[8];
    const float* ca_in_b = (const float*)d_in[9];
    const float* ca_ow   = (const float*)d_in[10];
    const float* ca_ob   = (const float*)d_in[11];
    const float* ln1w = (const float*)d_in[12];
    const float* ln1b = (const float*)d_in[13];
    const float* ln2w = (const float*)d_in[14];
    const float* ln2b = (const float*)d_in[15];
    const float* ln3w = (const float*)d_in[16];
    const float* ln3b = (const float*)d_in[17];
    const float* ff1w = (const float*)d_in[18];
    const float* ff1b = (const float*)d_in[19];
    const float* ff2w = (const float*)d_in[20];
    const float* ff2b = (const float*)d_in[21];

    float *srct, *srcpos, *kvall, *opart, *x, *qe, *qkv, *qb, *ao, *t2, *ffh;
    float2* mspart; unsigned* mbits;
    cudaGetSymbolAddress((void**)&srct, g_srct);
    cudaGetSymbolAddress((void**)&srcpos, g_srcpos);
    cudaGetSymbolAddress((void**)&mbits, g_mbits);
    cudaGetSymbolAddress((void**)&kvall, g_kvall);
    cudaGetSymbolAddress((void**)&opart, g_opart);
    cudaGetSymbolAddress((void**)&mspart, g_mspart);
    cudaGetSymbolAddress((void**)&x, g_x);
    cudaGetSymbolAddress((void**)&qe, g_qe);
    cudaGetSymbolAddress((void**)&qkv, g_qkv);
    cudaGetSymbolAddress((void**)&qb, g_qb);
    cudaGetSymbolAddress((void**)&ao, g_ao);
    cudaGetSymbolAddress((void**)&t2, g_t2);
    cudaGetSymbolAddress((void**)&ffh, g_ffh);

    cudaFuncSetAttribute(flash_ca, cudaFuncAttributeMaxDynamicSharedMemorySize,
                         FLASH_SMEM_BYTES);

    const float scale = 0.17677669529663687f;  // 32^-0.5
    const int C = C_MODEL, S = S_TOTAL;
    const int BIG = 1 << 30;

    // Slot 4 (profiled): layer-0 SA QKV — A/B of PAD=20 conflict-free gemmbf<64>
    prep_src<<<dim3((S + 31) / 32, C / 32), dim3(32, 8)>>>(srcs, pos, srct, srcpos);
    init_qx<<<NQ, 256>>>(qemb, qe, x);
    detect_mask<<<1, 256>>>((const unsigned int*)mask);
    gemmbf<64><<<gtile(NQ, 3 * C, 1, 64), 256>>>(            // <- profiled slot
        x, x, qe, 512, sa_in_w, sa_in_b, qkv,
        NQ, 3 * C, C, C, C, 3 * C, 0, 0, 0, 0, scale, C, 0);
    mask_to_bits<<<(NQ * SW + 255) / 256, 256>>>(mask, mbits);
    gemmbf<128><<<gtile(S, 512, NLAYERS, 128), 256>>>(
        srcpos, srct, nullptr, 256,
        ca_in_w + C * C, ca_in_b + C, kvall,
        S, 512, C, C, C, 512,
        0L, (long)3 * C * C, (long)3 * C, (long)S * 512,
        1.f, 0, 0);

    for (int l = 0; l < NLAYERS; l++) {
        const float* saw = sa_in_w + (long)l * 3 * C * C;
        const float* sab = sa_in_b + (long)l * 3 * C;
        const float* caw = ca_in_w + (long)l * 3 * C * C;
        const float* cab = ca_in_b + (long)l * 3 * C;
        const float* kvl = kvall + (long)l * S * 512;

        // ---- self attention ----
        if (l > 0) {
            gemmbf<64><<<gtile(NQ, 3 * C, 1, 64), 256>>>(
                x, x, qe, 512, saw, sab, qkv,
                NQ, 3 * C, C, C, C, 3 * C, 0, 0, 0, 0, scale, C, 0);
        }
        sa_attn<<<dim3(NHEADS, (NQ + 7) / 8), 256>>>(qkv, ao);
        gemmbf<64><<<gtile(NQ, C, 1, 64), 256>>>(
            ao, nullptr, nullptr, BIG, sa_ow + (long)l * C * C, sa_ob + (long)l * C, t2,
            NQ, C, C, C, C, C, 0, 0, 0, 0, 1.f, 0, 0);
        residual_ln<<<NQ, 256>>>(x, t2, ln2w + (long)l * C, ln2b + (long)l * C);

        // ---- cross attention (flash) ----
        gemmbf<64><<<gtile(NQ, C, 1, 64), 256>>>(
            x, nullptr, qe, BIG, caw, cab, qb,
            NQ, C, C, C, C, C, 0, 0, 0, 0, scale, C, 0);
        flash_ca<<<dim3(NCHUNK, NHEADS), 320, FLASH_SMEM_BYTES>>>(
            qb, kvl, mbits, opart, mspart);
        ca_combine<<<(NHEADS * NQ * 4 + 255) / 256, 256>>>(opart, mspart, ao);
        gemmbf<64><<<gtile(NQ, C, 1, 64), 256>>>(
            ao, nullptr, nullptr, BIG, ca_ow + (long)l * C * C, ca_ob + (long)l * C, t2,
            NQ, C, C, C, C, C, 0, 0, 0, 0, 1.f, 0, 0);
        residual_ln<<<NQ, 256>>>(x, t2, ln1w + (long)l * C, ln1b + (long)l * C);

        // ---- FFN ----
        gemmbf<64><<<gtile(NQ, DFF, 1, 64), 256>>>(
            x, nullptr, nullptr, BIG, ff1w + (long)l * DFF * C, ff1b + (long)l * DFF, ffh,
            NQ, DFF, C, C, C, DFF, 0, 0, 0, 0, 1.f, 0, 1);
        gemmbf<64><<<gtile(NQ, C, 1, 64), 256>>>(
            ffh, nullptr, nullptr, BIG, ff2w + (long)l * C * DFF, ff2b + (long)l * C, t2,
            NQ, C, DFF, DFF, DFF, C, 0, 0, 0, 0, 1.f, 0, 0);
        residual_ln<<<NQ, 256>>>(x, t2, ln3w + (long)l * C, ln3b + (long)l * C);
    }

    copy_out<<<(NQ * C + 255) / 256, 256>>>(x, (float*)d_out, NQ * C);
}

// round 16
// speedup vs baseline: 1.5254x; 1.0589x over previous
#include <cuda_runtime.h>
#include <cuda_bf16.h>

#define S_TOTAL 15768
#define NQ 300
#define C_MODEL 256
#define NHEADS 8
#define DHEAD 32
#define NLAYERS 6
#define DFF 1024
#define CHUNK 256
#define NCHUNK 62
#define SW 493
#define FLASH_SMEM_BYTES 65536
#define PAD 20

// ------------------------- scratch (device globals) -------------------------
__device__ float g_srct[S_TOTAL * C_MODEL];
__device__ float g_srcpos[S_TOTAL * C_MODEL];
__device__ unsigned g_mbits[NQ * SW];
__device__ float g_kvall[(size_t)NLAYERS * S_TOTAL * 512];
__device__ float g_opart[(size_t)NCHUNK * NHEADS * NQ * DHEAD];
__device__ float2 g_mspart[NCHUNK * NHEADS * NQ];
__device__ float g_x[NQ * C_MODEL];
__device__ float g_qe[NQ * C_MODEL];
__device__ float g_qkv[NQ * 3 * C_MODEL];
__device__ float g_qb[NQ * C_MODEL];
__device__ float g_ao[NQ * C_MODEL];
__device__ float g_t2[NQ * C_MODEL];
__device__ float g_ffh[NQ * DFF];
__device__ int   g_mask_float;
__device__ int   g_mask_byte;

// ------------------------- bf16x3 helpers -------------------------
__device__ __forceinline__ void split2(float x, float y, unsigned& hi, unsigned& lo)
{
    __nv_bfloat16 hx = __float2bfloat16(x);
    __nv_bfloat16 hy = __float2bfloat16(y);
    float rx = x - __bfloat162float(hx);
    float ry = y - __bfloat162float(hy);
    __nv_bfloat16 lx = __float2bfloat16(rx);
    __nv_bfloat16 ly = __float2bfloat16(ry);
    hi = (unsigned)__bfloat16_as_ushort(hx) | ((unsigned)__bfloat16_as_ushort(hy) << 16);
    lo = (unsigned)__bfloat16_as_ushort(lx) | ((unsigned)__bfloat16_as_ushort(ly) << 16);
}

__device__ __forceinline__ void mma16(float c[4], const unsigned a[4], const unsigned b[2])
{
    asm volatile(
        "mma.sync.aligned.m16n8k16.row.col.f32.bf16.bf16.f32 "
        "{%0,%1,%2,%3}, {%4,%5,%6,%7}, {%8,%9}, {%0,%1,%2,%3};"
        : "+f"(c[0]), "+f"(c[1]), "+f"(c[2]), "+f"(c[3])
        : "r"(a[0]), "r"(a[1]), "r"(a[2]), "r"(a[3]), "r"(b[0]), "r"(b[1]));
}

// ------------------------- pipelined, double-buffered bf16x3 GEMM -------------------------
template <int BM>
__global__ __launch_bounds__(256) void gemmbf(
    const float* __restrict__ A0, const float* __restrict__ A1,
    const float* __restrict__ Aadd, int nsplit,
    const float* __restrict__ B, const float* __restrict__ bias,
    float* __restrict__ Cc, int M, int N, int K,
    int lda, int ldb, int ldc,
    long sA, long sB, long sbias, long sC,
    float alpha, int nscale, int relu)
{
    constexpr int BN = 64;
    constexpr int WMR = BM / 4;
    constexpr int MT = WMR / 16;
    constexpr int NT = 4;
    constexpr int NAROW = BM / 32;
    constexpr int NB = (BM == 64) ? 2 : 1;
    __shared__ unsigned Ah[NB][BM][PAD], Al[NB][BM][PAD];
    __shared__ unsigned Bh[NB][BN][PAD], Bl[NB][BN][PAD];

    int z = blockIdx.z;
    int m0 = blockIdx.y * BM, n0 = blockIdx.x * BN;
    const float* A = ((n0 >= nsplit) ? A1 : A0) + (long)z * sA;
    const float* Aa = (n0 < nsplit) ? Aadd : nullptr;
    const float* Bp = B + (long)z * sB;
    const float* bp = bias ? bias + (long)z * sbias : nullptr;
    float* Cp = Cc + (long)z * sC;

    int tid = threadIdx.x;
    int warp = tid >> 5, lane = tid & 31;
    int gid = lane >> 2, ctg = lane & 3;
    int wm = warp & 3, wn = warp >> 2;
    int mw = wm * WMR, nw = wn * 32;
    int lr = tid >> 3, lc4 = tid & 7;

    float acc[MT][NT][4] = {};
    float4 pa[NAROW], pb[2];

    #pragma unroll
    for (int i = 0; i < NAROW; i++) {
        int row = i * 32 + lr;
        float4 v = make_float4(0.f, 0.f, 0.f, 0.f);
        if (m0 + row < M) {
            v = *(const float4*)&A[(long)(m0 + row) * lda + lc4 * 4];
            if (Aa) {
                float4 w = *(const float4*)&Aa[(long)(m0 + row) * lda + lc4 * 4];
                v.x += w.x; v.y += w.y; v.z += w.z; v.w += w.w;
            }
        }
        pa[i] = v;
    }
    #pragma unroll
    for (int i = 0; i < 2; i++) {
        int row = i * 32 + lr;
        pb[i] = make_float4(0.f, 0.f, 0.f, 0.f);
        if (n0 + row < N)
            pb[i] = *(const float4*)&Bp[(long)(n0 + row) * ldb + lc4 * 4];
    }

    int bsel = 0;
    for (int k0 = 0; k0 < K; k0 += 32) {
        if (NB == 1) __syncthreads();
        #pragma unroll
        for (int i = 0; i < NAROW; i++) {
            int row = i * 32 + lr;
            unsigned h0, l0, h1, l1;
            split2(pa[i].x, pa[i].y, h0, l0);
            split2(pa[i].z, pa[i].w, h1, l1);
            Ah[bsel][row][lc4 * 2] = h0;     Al[bsel][row][lc4 * 2] = l0;
            Ah[bsel][row][lc4 * 2 + 1] = h1; Al[bsel][row][lc4 * 2 + 1] = l1;
        }
        #pragma unroll
        for (int i = 0; i < 2; i++) {
            int row = i * 32 + lr;
            unsigned h0, l0, h1, l1;
            split2(pb[i].x, pb[i].y, h0, l0);
            split2(pb[i].z, pb[i].w, h1, l1);
            Bh[bsel][row][lc4 * 2] = h0;     Bl[bsel][row][lc4 * 2] = l0;
            Bh[bsel][row][lc4 * 2 + 1] = h1; Bl[bsel][row][lc4 * 2 + 1] = l1;
        }
        __syncthreads();

        int kn = k0 + 32;
        if (kn < K) {
            #pragma unroll
            for (int i = 0; i < NAROW; i++) {
                int row = i * 32 + lr;
                float4 v = make_float4(0.f, 0.f, 0.f, 0.f);
                if (m0 + row < M) {
                    v = *(const float4*)&A[(long)(m0 + row) * lda + kn + lc4 * 4];
                    if (Aa) {
                        float4 w = *(const float4*)&Aa[(long)(m0 + row) * lda + kn + lc4 * 4];
                        v.x += w.x; v.y += w.y; v.z += w.z; v.w += w.w;
                    }
                }
                pa[i] = v;
            }
            #pragma unroll
            for (int i = 0; i < 2; i++) {
                int row = i * 32 + lr;
                float4 v = make_float4(0.f, 0.f, 0.f, 0.f);
                if (n0 + row < N)
                    v = *(const float4*)&Bp[(long)(n0 + row) * ldb + kn + lc4 * 4];
                pb[i] = v;
            }
        }

        #pragma unroll
        for (int st = 0; st < 2; st++) {
            int kc = st * 8;
            unsigned bh[NT][2], bl[NT][2];
            #pragma unroll
            for (int nt = 0; nt < NT; nt++) {
                int row = nw + nt * 8 + gid;
                bh[nt][0] = Bh[bsel][row][kc + ctg];
                bh[nt][1] = Bh[bsel][row][kc + ctg + 4];
                bl[nt][0] = Bl[bsel][row][kc + ctg];
                bl[nt][1] = Bl[bsel][row][kc + ctg + 4];
            }
            #pragma unroll
            for (int mt = 0; mt < MT; mt++) {
                int r0 = mw + mt * 16 + gid, r1 = r0 + 8;
                unsigned ah[4], al[4];
                ah[0] = Ah[bsel][r0][kc + ctg];     ah[1] = Ah[bsel][r1][kc + ctg];
                ah[2] = Ah[bsel][r0][kc + ctg + 4]; ah[3] = Ah[bsel][r1][kc + ctg + 4];
                al[0] = Al[bsel][r0][kc + ctg];     al[1] = Al[bsel][r1][kc + ctg];
                al[2] = Al[bsel][r0][kc + ctg + 4]; al[3] = Al[bsel][r1][kc + ctg + 4];
                #pragma unroll
                for (int nt = 0; nt < NT; nt++) {
                    mma16(acc[mt][nt], ah, bh[nt]);
                    mma16(acc[mt][nt], al, bh[nt]);
                    mma16(acc[mt][nt], ah, bl[nt]);
                }
            }
        }
        bsel ^= (NB - 1);
    }

    #pragma unroll
    for (int mt = 0; mt < MT; mt++) {
        #pragma unroll
        for (int nt = 0; nt < NT; nt++) {
            #pragma unroll
            for (int e = 0; e < 4; e++) {
                int m = m0 + mw + mt * 16 + gid + (e >> 1) * 8;
                int n = n0 + nw + nt * 8 + 2 * ctg + (e & 1);
                if (m >= M || n >= N) continue;
                float v = acc[mt][nt][e];
                if (bp) v += bp[n];
                if (n < nscale) v *= alpha;
                if (relu) v = fmaxf(v, 0.f);
                Cp[(long)m * ldc + n] = v;
            }
        }
    }
}

// ------------------------- residual + LayerNorm -------------------------
__global__ __launch_bounds__(256) void residual_ln(
    float* __restrict__ x, const float* __restrict__ res,
    const float* __restrict__ w, const float* __restrict__ b)
{
    int r = blockIdx.x;
    int c = threadIdx.x;
    float v = x[r * 256 + c] + res[r * 256 + c];
    __shared__ float red[256];
    red[c] = v; __syncthreads();
    for (int off = 128; off > 0; off >>= 1) { if (c < off) red[c] += red[c + off]; __syncthreads(); }
    float mean = red[0] * (1.f / 256.f);
    __syncthreads();
    float d = v - mean;
    red[c] = d * d; __syncthreads();
    for (int off = 128; off > 0; off >>= 1) { if (c < off) red[c] += red[c + off]; __syncthreads(); }
    float var = red[0] * (1.f / 256.f);
    x[r * 256 + c] = d * rsqrtf(var + 1e-5f) * w[c] + b[c];
}

// ------------------------- fused self-attention (scores in log2 domain) -------------------------
__global__ __launch_bounds__(256) void sa_attn(const float* __restrict__ qkv,
                                               float* __restrict__ ao)
{
    int h = blockIdx.x;
    int w = threadIdx.x >> 5;
    int lane = threadIdx.x & 31;
    int q = blockIdx.y * 8 + w;
    __shared__ float Qs[8][32];
    if (q < NQ) Qs[w][lane] = qkv[(long)q * 768 + h * 32 + lane];
    __syncwarp();
    if (q >= NQ) return;

    float m = -3.4e38f, s = 0.f, O[32] = {};
    for (int k = lane; k < NQ; k += 32) {
        const float4* Kp = (const float4*)&qkv[(long)k * 768 + 256 + h * 32];
        float d = 0.f;
        #pragma unroll
        for (int f = 0; f < 8; f++) {
            float4 kk = Kp[f];
            d += Qs[w][4*f]*kk.x + Qs[w][4*f+1]*kk.y + Qs[w][4*f+2]*kk.z + Qs[w][4*f+3]*kk.w;
        }
        float p;
        if (d > m) {
            float c = exp2f(m - d);
            s = s * c + 1.f;
            #pragma unroll
            for (int i = 0; i < 32; i++) O[i] *= c;
            m = d; p = 1.f;
        } else { p = exp2f(d - m); s += p; }
        const float4* Vp = (const float4*)&qkv[(long)k * 768 + 512 + h * 32];
        #pragma unroll
        for (int f = 0; f < 8; f++) {
            float4 vv = Vp[f];
            O[4*f]   += p * vv.x; O[4*f+1] += p * vv.y;
            O[4*f+2] += p * vv.z; O[4*f+3] += p * vv.w;
        }
    }
    float mg = m;
    #pragma unroll
    for (int o = 16; o; o >>= 1) mg = fmaxf(mg, __shfl_xor_sync(0xffffffffu, mg, o));
    float c = exp2f(m - mg);
    s *= c;
    #pragma unroll
    for (int o = 16; o; o >>= 1) s += __shfl_xor_sync(0xffffffffu, s, o);
    float mine = 0.f;
    #pragma unroll
    for (int d = 0; d < 32; d++) {
        float v = O[d] * c;
        #pragma unroll
        for (int o = 16; o; o >>= 1) v += __shfl_xor_sync(0xffffffffu, v, o);
        if (lane == d) mine = v;
    }
    ao[(long)q * 256 + h * 32 + lane] = mine / s;
}

// ------------------------- flash cross-attention (log2 domain) -------------------------
__global__ __launch_bounds__(320, 1) void flash_ca(
    const float* __restrict__ Qm,
    const float* __restrict__ KV,
    const unsigned* __restrict__ mbits,
    float* __restrict__ Opart, float2* __restrict__ MSpart)
{
    extern __shared__ __align__(16) float4 sh[];
    float4 (*Ks)[8] = (float4(*)[8])sh;
    float4 (*Vs)[8] = (float4(*)[8])(sh + CHUNK * 8);
    int ch = blockIdx.x, h = blockIdx.y;
    int s0 = ch * CHUNK;
    int nk = min(CHUNK, S_TOTAL - s0);
    int tid = threadIdx.x;
    for (int idx = tid; idx < nk * 8; idx += 320) {
        int j = idx >> 3, f = idx & 7;
        const float4* row = (const float4*)&KV[(long)(s0 + j) * 512];
        Ks[j][f] = row[h * 8 + f];
        Vs[j][f] = row[64 + h * 8 + f];
    }
    __syncthreads();

    int q = tid;
    if (q >= NQ) return;

    float Q[32], O[32] = {};
    #pragma unroll
    for (int f = 0; f < 8; f++)
        ((float4*)Q)[f] = *(const float4*)&Qm[(long)q * 256 + h * 32 + f * 4];
    float m = -3.4e38f, s = 0.f;

    for (int jw = 0; jw < nk; jw += 32) {
        unsigned w = mbits[q * SW + ((s0 + jw) >> 5)];
        while (w) {
            int jj = __ffs(w) - 1;
            w &= w - 1;
            int j = jw + jj;
            float d = 0.f;
            #pragma unroll
            for (int f = 0; f < 8; f++) {
                float4 kk = Ks[j][f];
                d += Q[4*f]*kk.x + Q[4*f+1]*kk.y + Q[4*f+2]*kk.z + Q[4*f+3]*kk.w;
            }
            float p;
            if (d > m) {
                float c = exp2f(m - d);
                s = s * c + 1.f;
                #pragma unroll
                for (int i = 0; i < 32; i++) O[i] *= c;
                m = d; p = 1.f;
            } else { p = exp2f(d - m); s += p; }
            #pragma unroll
            for (int f = 0; f < 8; f++) {
                float4 vv = Vs[j][f];
                O[4*f]   += p * vv.x; O[4*f+1] += p * vv.y;
                O[4*f+2] += p * vv.z; O[4*f+3] += p * vv.w;
            }
        }
    }
    long base = (long)(ch * NHEADS + h) * NQ + q;
    float4* op = (float4*)&Opart[base * DHEAD];
    #pragma unroll
    for (int f = 0; f < 8; f++) op[f] = ((float4*)O)[f];
    MSpart[base] = make_float2(m, s);
}

// ------------------------- combine (log2 domain, 4-way split over head dim) -------------------------
__global__ void ca_combine(const float* __restrict__ Opart,
                           const float2* __restrict__ MSpart,
                           float* __restrict__ ao)
{
    int idx = blockIdx.x * blockDim.x + threadIdx.x;
    if (idx >= NHEADS * NQ * 4) return;
    int dg = idx & 3;
    int hq = idx >> 2;
    int h = hq / NQ, q = hq % NQ;
    float m = -3.4e38f, s = 0.f;
    float O[8] = {};
    for (int ch = 0; ch < NCHUNK; ch++) {
        long base = (long)(ch * NHEADS + h) * NQ + q;
        float2 ms = MSpart[base];
        if (ms.y <= 0.f) continue;
        float c2;
        if (ms.x > m) {
            float c = (m > -3.0e38f) ? exp2f(m - ms.x) : 0.f;
            s *= c;
            #pragma unroll
            for (int d = 0; d < 8; d++) O[d] *= c;
            m = ms.x;
            c2 = 1.f;
        } else {
            c2 = exp2f(ms.x - m);
        }
        s += ms.y * c2;
        const float4* op = (const float4*)&Opart[base * DHEAD + dg * 8];
        float4 v0 = op[0], v1 = op[1];
        O[0] += c2 * v0.x; O[1] += c2 * v0.y; O[2] += c2 * v0.z; O[3] += c2 * v0.w;
        O[4] += c2 * v1.x; O[5] += c2 * v1.y; O[6] += c2 * v1.z; O[7] += c2 * v1.w;
    }
    float inv = 1.f / s;
    float4* outp = (float4*)&ao[(long)q * 256 + h * 32 + dg * 8];
    outp[0] = make_float4(O[0] * inv, O[1] * inv, O[2] * inv, O[3] * inv);
    outp[1] = make_float4(O[4] * inv, O[5] * inv, O[6] * inv, O[7] * inv);
}

// ------------------------- small kernels -------------------------
__global__ void prep_src(const float* __restrict__ srcs, const float* __restrict__ pos,
                         float* __restrict__ srct, float* __restrict__ srcpos)
{
    __shared__ float t1[32][33], t2[32][33];
    int s0 = blockIdx.x * 32, c0 = blockIdx.y * 32;
    int tx = threadIdx.x, ty = threadIdx.y;
    #pragma unroll
    for (int i = 0; i < 4; i++) {
        int c = c0 + ty + i * 8, s = s0 + tx;
        float a = 0.f, f = 0.f;
        if (s < S_TOTAL) { a = srcs[(long)c * S_TOTAL + s]; f = pos[(long)c * S_TOTAL + s]; }
        t1[ty + i * 8][tx] = a;
        t2[ty + i * 8][tx] = f;
    }
    __syncthreads();
    #pragma unroll
    for (int i = 0; i < 4; i++) {
        int s = s0 + ty + i * 8, c = c0 + tx;
        if (s < S_TOTAL) {
            float a = t1[tx][ty + i * 8];
            float f = t2[tx][ty + i * 8];
            srct[(long)s * 256 + c]   = a;
            srcpos[(long)s * 256 + c] = a + f;
        }
    }
}

__global__ void init_qx(const float* __restrict__ qemb, float* __restrict__ qe, float* __restrict__ x)
{
    int r = blockIdx.x, c = threadIdx.x;
    qe[r * 256 + c] = qemb[r * 512 + c];
    x[r * 256 + c]  = qemb[r * 512 + 256 + c];
}

__global__ void detect_mask(const unsigned int* __restrict__ w)
{
    if (threadIdx.x == 0) { g_mask_float = 0; g_mask_byte = 0; }
    __syncthreads();
    int fl = 0, by = 0;
    for (int i = threadIdx.x; i < 65536; i += 256) {
        unsigned int v = w[i];
        if (v == 0x3F800000u) fl = 1;
        else if (v > 1u) by = 1;
    }
    if (fl) atomicOr(&g_mask_float, 1);
    if (by) atomicOr(&g_mask_byte, 1);
}

__global__ void mask_to_bits(const void* __restrict__ mask, unsigned* __restrict__ bits)
{
    int idx = blockIdx.x * 256 + threadIdx.x;
    if (idx >= NQ * SW) return;
    int q = idx / SW, w = idx % SW;
    unsigned out = 0;
    int base = w * 32;
    int fl = g_mask_float, by = g_mask_byte;
    #pragma unroll 4
    for (int j = 0; j < 32; j++) {
        int s = base + j;
        if (s >= S_TOTAL) break;
        long off = (long)q * S_TOTAL + s;
        int blocked;
        if (fl)      blocked = ((const float*)mask)[off] != 0.f;
        else if (by) blocked = ((const unsigned char*)mask)[off] != 0;
        else         blocked = ((const int*)mask)[off] != 0;
        if (!blocked) out |= 1u << j;
    }
    bits[idx] = out;
}

__global__ void copy_out(const float* __restrict__ x, float* __restrict__ out, int n)
{
    int i = blockIdx.x * 256 + threadIdx.x;
    if (i < n) out[i] = x[i];
}

// ------------------------- host driver -------------------------
static inline dim3 gtile(int M, int N, int z, int BM) {
    return dim3((N + 63) / 64, (M + BM - 1) / BM, z);
}

extern "C" void kernel_launch(void* const* d_in, const int* in_sizes, int n_in,
                              void* d_out, int out_size)
{
    const float* srcs    = (const float*)d_in[0];
    const float* pos     = (const float*)d_in[1];
    const float* qemb    = (const float*)d_in[2];
    const void*  mask    = d_in[3];
    const float* sa_in_w = (const float*)d_in[4];
    const float* sa_in_b = (const float*)d_in[5];
    const float* sa_ow   = (const float*)d_in[6];
    const float* sa_ob   = (const float*)d_in[7];
    const float* ca_in_w = (const float*)d_in[8];
    const float* ca_in_b = (const float*)d_in[9];
    const float* ca_ow   = (const float*)d_in[10];
    const float* ca_ob   = (const float*)d_in[11];
    const float* ln1w = (const float*)d_in[12];
    const float* ln1b = (const float*)d_in[13];
    const float* ln2w = (const float*)d_in[14];
    const float* ln2b = (const float*)d_in[15];
    const float* ln3w = (const float*)d_in[16];
    const float* ln3b = (const float*)d_in[17];
    const float* ff1w = (const float*)d_in[18];
    const float* ff1b = (const float*)d_in[19];
    const float* ff2w = (const float*)d_in[20];
    const float* ff2b = (const float*)d_in[21];

    float *srct, *srcpos, *kvall, *opart, *x, *qe, *qkv, *qb, *ao, *t2, *ffh;
    float2* mspart; unsigned* mbits;
    cudaGetSymbolAddress((void**)&srct, g_srct);
    cudaGetSymbolAddress((void**)&srcpos, g_srcpos);
    cudaGetSymbolAddress((void**)&mbits, g_mbits);
    cudaGetSymbolAddress((void**)&kvall, g_kvall);
    cudaGetSymbolAddress((void**)&opart, g_opart);
    cudaGetSymbolAddress((void**)&mspart, g_mspart);
    cudaGetSymbolAddress((void**)&x, g_x);
    cudaGetSymbolAddress((void**)&qe, g_qe);
    cudaGetSymbolAddress((void**)&qkv, g_qkv);
    cudaGetSymbolAddress((void**)&qb, g_qb);
    cudaGetSymbolAddress((void**)&ao, g_ao);
    cudaGetSymbolAddress((void**)&t2, g_t2);
    cudaGetSymbolAddress((void**)&ffh, g_ffh);

    cudaFuncSetAttribute(flash_ca, cudaFuncAttributeMaxDynamicSharedMemorySize,
                         FLASH_SMEM_BYTES);

    const float LOG2E = 1.4426950408889634f;
    const float scale = 0.17677669529663687f;           // 32^-0.5
    const float scl2 = scale * LOG2E;                   // q pre-scale for exp2 softmax
    const int C = C_MODEL, S = S_TOTAL;
    const int BIG = 1 << 30;

    // fork side stream for mask prep + per-layer KV projection
    cudaStream_t s2;
    cudaStreamCreate(&s2);
    cudaEvent_t efork, ekv[NLAYERS];
    cudaEventCreateWithFlags(&efork, cudaEventDisableTiming);
    for (int l = 0; l < NLAYERS; l++)
        cudaEventCreateWithFlags(&ekv[l], cudaEventDisableTiming);

    // main: prep + init
    prep_src<<<dim3((S + 31) / 32, C / 32), dim3(32, 8)>>>(srcs, pos, srct, srcpos);
    cudaEventRecord(efork, 0);
    init_qx<<<NQ, 256>>>(qemb, qe, x);

    // side: detect -> mask bits -> per-layer KV (each followed by its event)
    cudaStreamWaitEvent(s2, efork, 0);
    detect_mask<<<1, 256, 0, s2>>>((const unsigned int*)mask);
    mask_to_bits<<<(NQ * SW + 255) / 256, 256, 0, s2>>>(mask, mbits);
    for (int l = 0; l < NLAYERS; l++) {
        gemmbf<128><<<gtile(S, 512, 1, 128), 256, 0, s2>>>(
            srcpos, srct, nullptr, 256,
            ca_in_w + (long)l * 3 * C * C + C * C,
            ca_in_b + (long)l * 3 * C + C,
            kvall + (long)l * S * 512,
            S, 512, C, C, C, 512,
            0L, 0L, 0L, 0L, 1.f, 0, 0);
        cudaEventRecord(ekv[l], s2);
    }

    for (int l = 0; l < NLAYERS; l++) {
        const float* saw = sa_in_w + (long)l * 3 * C * C;
        const float* sab = sa_in_b + (long)l * 3 * C;
        const float* caw = ca_in_w + (long)l * 3 * C * C;
        const float* cab = ca_in_b + (long)l * 3 * C;
        const float* kvl = kvall + (long)l * S * 512;

        // ---- self attention ---- (q scaled by scale*log2e; sa_attn uses exp2)
        gemmbf<64><<<gtile(NQ, 3 * C, 1, 64), 256>>>(
            x, x, qe, 512, saw, sab, qkv,
            NQ, 3 * C, C, C, C, 3 * C, 0, 0, 0, 0, scl2, C, 0);
        sa_attn<<<dim3(NHEADS, (NQ + 7) / 8), 256>>>(qkv, ao);
        gemmbf<64><<<gtile(NQ, C, 1, 64), 256>>>(
            ao, nullptr, nullptr, BIG, sa_ow + (long)l * C * C, sa_ob + (long)l * C, t2,
            NQ, C, C, C, C, C, 0, 0, 0, 0, 1.f, 0, 0);
        residual_ln<<<NQ, 256>>>(x, t2, ln2w + (long)l * C, ln2b + (long)l * C);

        // ---- cross attention (flash) ----
        gemmbf<64><<<gtile(NQ, C, 1, 64), 256>>>(
            x, nullptr, qe, BIG, caw, cab, qb,
            NQ, C, C, C, C, C, 0, 0, 0, 0, scl2, C, 0);
        cudaStreamWaitEvent(0, ekv[l], 0);   // join: layer-l KV (and mask bits) ready
        flash_ca<<<dim3(NCHUNK, NHEADS), 320, FLASH_SMEM_BYTES>>>(
            qb, kvl, mbits, opart, mspart);
        ca_combine<<<(NHEADS * NQ * 4 + 255) / 256, 256>>>(opart, mspart, ao);
        gemmbf<64><<<gtile(NQ, C, 1, 64), 256>>>(
            ao, nullptr, nullptr, BIG, ca_ow + (long)l * C * C, ca_ob + (long)l * C, t2,
            NQ, C, C, C, C, C, 0, 0, 0, 0, 1.f, 0, 0);
        residual_ln<<<NQ, 256>>>(x, t2, ln1w + (long)l * C, ln1b + (long)l * C);

        // ---- FFN ----
        gemmbf<64><<<gtile(NQ, DFF, 1, 64), 256>>>(
            x, nullptr, nullptr, BIG, ff1w + (long)l * DFF * C, ff1b + (long)l * DFF, ffh,
            NQ, DFF, C, C, C, DFF, 0, 0, 0, 0, 1.f, 0, 1);
        gemmbf<64><<<gtile(NQ, C, 1, 64), 256>>>(
            ffh, nullptr, nullptr, BIG, ff2w + (long)l * C * DFF, ff2b + (long)l * C, t2,
            NQ, C, DFF, DFF, DFF, C, 0, 0, 0, 0, 1.f, 0, 0);
        residual_ln<<<NQ, 256>>>(x, t2, ln3w + (long)l * C, ln3b + (long)l * C);
    }

    copy_out<<<(NQ * C + 255) / 256, 256>>>(x, (float*)d_out, NQ * C);
}